// round 1
// baseline (speedup 1.0000x reference)
#include <cuda_runtime.h>
#include <math.h>

#define T_LEN   1024
#define DMODEL  1024
#define QDIM    4096
#define HQ      64
#define HK      16
#define DH      64
#define SILU_SCALE 1.8137993642342178f   /* pi / sqrt(3) */
#define ATTN_SCALE 0.125f                /* DH^-0.5 */

static __device__ float g_Q[T_LEN * QDIM];
static __device__ float g_K[T_LEN * DMODEL];
static __device__ float g_V[T_LEN * DMODEL];
static __device__ float g_OUT[T_LEN * QDIM];
static __device__ float g_part[4 * T_LEN * DMODEL];

// ---------------------------------------------------------------------------
// SGEMM: C = A(MxK) @ B(KxN) + bias[N].  blockIdx.z selects (B0,bias0,C0) or
// (B1,bias1,C1) so K and V projections share one launch (more blocks in flight).
// 128x128 tile, BK=8, 256 threads, 8x8 microtile.
// ---------------------------------------------------------------------------
__global__ __launch_bounds__(256)
void sgemm_bias_kernel(const float* __restrict__ A,
                       const float* __restrict__ B0, const float* __restrict__ B1,
                       const float* __restrict__ bias0, const float* __restrict__ bias1,
                       float* __restrict__ C0, float* __restrict__ C1,
                       int M, int N, int K)
{
    const float* B    = (blockIdx.z == 0) ? B0    : B1;
    const float* bias = (blockIdx.z == 0) ? bias0 : bias1;
    float*       C    = (blockIdx.z == 0) ? C0    : C1;

    __shared__ float As[8][128];
    __shared__ float Bs[8][128];

    int tid  = threadIdx.x;
    int tx   = tid & 15;
    int ty   = tid >> 4;
    int arow = tid >> 1;
    int acol = (tid & 1) << 2;
    int brow = tid >> 5;
    int bcol = (tid & 31) << 2;

    const float* Aptr = A + (size_t)(blockIdx.y * 128 + arow) * K + acol;
    const float* Bptr = B + (size_t)brow * N + blockIdx.x * 128 + bcol;

    float acc[8][8];
#pragma unroll
    for (int i = 0; i < 8; ++i)
#pragma unroll
        for (int j = 0; j < 8; ++j) acc[i][j] = 0.f;

    for (int k0 = 0; k0 < K; k0 += 8) {
        float4 av = *(const float4*)(Aptr + k0);
        float4 bv = *(const float4*)(Bptr + (size_t)k0 * N);
        As[acol + 0][arow] = av.x;
        As[acol + 1][arow] = av.y;
        As[acol + 2][arow] = av.z;
        As[acol + 3][arow] = av.w;
        *(float4*)&Bs[brow][bcol] = bv;
        __syncthreads();
#pragma unroll
        for (int kk = 0; kk < 8; ++kk) {
            float af[8], bf[8];
            *(float4*)&af[0] = *(const float4*)&As[kk][ty * 8];
            *(float4*)&af[4] = *(const float4*)&As[kk][ty * 8 + 4];
            *(float4*)&bf[0] = *(const float4*)&Bs[kk][tx * 8];
            *(float4*)&bf[4] = *(const float4*)&Bs[kk][tx * 8 + 4];
#pragma unroll
            for (int i = 0; i < 8; ++i)
#pragma unroll
                for (int j = 0; j < 8; ++j)
                    acc[i][j] = fmaf(af[i], bf[j], acc[i][j]);
        }
        __syncthreads();
    }

    int row0 = blockIdx.y * 128 + ty * 8;
    int col0 = blockIdx.x * 128 + tx * 8;
    float bv0[8];
#pragma unroll
    for (int j = 0; j < 8; ++j) bv0[j] = bias[col0 + j];
#pragma unroll
    for (int i = 0; i < 8; ++i) {
        float4 o0, o1;
        o0.x = acc[i][0] + bv0[0]; o0.y = acc[i][1] + bv0[1];
        o0.z = acc[i][2] + bv0[2]; o0.w = acc[i][3] + bv0[3];
        o1.x = acc[i][4] + bv0[4]; o1.y = acc[i][5] + bv0[5];
        o1.z = acc[i][6] + bv0[6]; o1.w = acc[i][7] + bv0[7];
        *(float4*)&C[(size_t)(row0 + i) * N + col0]     = o0;
        *(float4*)&C[(size_t)(row0 + i) * N + col0 + 4] = o1;
    }
}

// ---------------------------------------------------------------------------
// Split-K SGEMM (no bias): each z computes a K-slice into its own partial
// buffer; used for the output projection (K=4096 -> 4 slices, 256 blocks).
// ---------------------------------------------------------------------------
__global__ __launch_bounds__(256)
void sgemm_splitk_kernel(const float* __restrict__ A, const float* __restrict__ B,
                         float* __restrict__ Cpart, int M, int N, int Ktot, int kPer)
{
    int z = blockIdx.z;
    A += (size_t)z * kPer;
    B += (size_t)z * kPer * N;
    Cpart += (size_t)z * M * N;

    __shared__ float As[8][128];
    __shared__ float Bs[8][128];

    int tid  = threadIdx.x;
    int tx   = tid & 15;
    int ty   = tid >> 4;
    int arow = tid >> 1;
    int acol = (tid & 1) << 2;
    int brow = tid >> 5;
    int bcol = (tid & 31) << 2;

    const float* Aptr = A + (size_t)(blockIdx.y * 128 + arow) * Ktot + acol;
    const float* Bptr = B + (size_t)brow * N + blockIdx.x * 128 + bcol;

    float acc[8][8];
#pragma unroll
    for (int i = 0; i < 8; ++i)
#pragma unroll
        for (int j = 0; j < 8; ++j) acc[i][j] = 0.f;

    for (int k0 = 0; k0 < kPer; k0 += 8) {
        float4 av = *(const float4*)(Aptr + k0);
        float4 bv = *(const float4*)(Bptr + (size_t)k0 * N);
        As[acol + 0][arow] = av.x;
        As[acol + 1][arow] = av.y;
        As[acol + 2][arow] = av.z;
        As[acol + 3][arow] = av.w;
        *(float4*)&Bs[brow][bcol] = bv;
        __syncthreads();
#pragma unroll
        for (int kk = 0; kk < 8; ++kk) {
            float af[8], bf[8];
            *(float4*)&af[0] = *(const float4*)&As[kk][ty * 8];
            *(float4*)&af[4] = *(const float4*)&As[kk][ty * 8 + 4];
            *(float4*)&bf[0] = *(const float4*)&Bs[kk][tx * 8];
            *(float4*)&bf[4] = *(const float4*)&Bs[kk][tx * 8 + 4];
#pragma unroll
            for (int i = 0; i < 8; ++i)
#pragma unroll
                for (int j = 0; j < 8; ++j)
                    acc[i][j] = fmaf(af[i], bf[j], acc[i][j]);
        }
        __syncthreads();
    }

    int row0 = blockIdx.y * 128 + ty * 8;
    int col0 = blockIdx.x * 128 + tx * 8;
#pragma unroll
    for (int i = 0; i < 8; ++i) {
        float4 o0, o1;
        o0.x = acc[i][0]; o0.y = acc[i][1]; o0.z = acc[i][2]; o0.w = acc[i][3];
        o1.x = acc[i][4]; o1.y = acc[i][5]; o1.z = acc[i][6]; o1.w = acc[i][7];
        *(float4*)&Cpart[(size_t)(row0 + i) * N + col0]     = o0;
        *(float4*)&Cpart[(size_t)(row0 + i) * N + col0 + 4] = o1;
    }
}

// ---------------------------------------------------------------------------
// RoPE (in place) on Q (64 heads) and K (16 heads). For K also computes
// key_self = clip(|k|^2,1e-6) and folds ATTN_SCALE/sqrt(key_self) into the
// stored K rows, so attention scores come out ready for softplus.
// One warp handles one (t, head-slot); lane j handles pair (2j, 2j+1).
// ---------------------------------------------------------------------------
__global__ __launch_bounds__(256)
void rope_kernel(float* __restrict__ Q, float* __restrict__ K)
{
    int gw   = blockIdx.x * 8 + (threadIdx.x >> 5);
    int lane = threadIdx.x & 31;
    int slot = gw % (HQ + HK);
    int t    = gw / (HQ + HK);

    bool isK = (slot >= HQ);
    float* ptr = isK ? (K + (size_t)t * DMODEL + (slot - HQ) * DH)
                     : (Q + (size_t)t * QDIM + slot * DH);

    float x1 = ptr[2 * lane];
    float x2 = ptr[2 * lane + 1];

    float inv = 1.0f / powf(10000.0f, (float)(2 * lane) / 64.0f);
    float fr  = (float)t * inv;
    float s, c;
    sincosf(fr, &s, &c);

    float o1 = x1 * c - x2 * s;
    float o2 = x1 * s + x2 * c;

    if (isK) {
        float nrm = x1 * x1 + x2 * x2;   // rotation preserves pair norms
#pragma unroll
        for (int off = 16; off; off >>= 1)
            nrm += __shfl_xor_sync(0xffffffffu, nrm, off);
        float ks  = fmaxf(nrm, 1e-6f);
        float scl = ATTN_SCALE * rsqrtf(ks);
        o1 *= scl;
        o2 *= scl;
    }
    __syncwarp();
    ptr[lane]      = o1;
    ptr[lane + 32] = o2;
}

// ---------------------------------------------------------------------------
// Attention: one block = (head, 64-query tile). Streams causal 64-key tiles:
// scores -> softplus*sigmoid gate -> sink threshold -> accumulate w@V and
// row-sums (no softmax => no rescaling). Epilogue: (acc + sink*v_null)/total.
// Shared: Qs[64][65] + KV[64][65] (K then reused for V) + Ws[64][65].
// ---------------------------------------------------------------------------
#define LDP 65
__global__ __launch_bounds__(256)
void attn_kernel(const float* __restrict__ sinks, const float* __restrict__ v_nulls)
{
    extern __shared__ float sm[];
    float* Qs  = sm;                 // 64*LDP
    float* KVs = Qs + 64 * LDP;      // 64*LDP
    float* Ws  = KVs + 64 * LDP;     // 64*LDP

    int head = blockIdx.y;
    int qt   = blockIdx.x;
    int kvh  = head & (HK - 1);
    int tid  = threadIdx.x;
    int tx   = tid & 15;
    int ty   = tid >> 4;
    float sink = sinks[head];

    // load Q tile (rows = local query, cols = head dim)
    {
        int r  = tid >> 4;
        int c4 = (tid & 15) * 4;
#pragma unroll
        for (int it = 0; it < 4; ++it) {
            int row = r + it * 16;
            float4 v = *(const float4*)&g_Q[(size_t)(qt * 64 + row) * QDIM + head * DH + c4];
            Qs[row * LDP + c4 + 0] = v.x;
            Qs[row * LDP + c4 + 1] = v.y;
            Qs[row * LDP + c4 + 2] = v.z;
            Qs[row * LDP + c4 + 3] = v.w;
        }
    }

    float acc[4][4];
    float rsum[4];
#pragma unroll
    for (int r = 0; r < 4; ++r) {
        rsum[r] = 0.f;
#pragma unroll
        for (int c = 0; c < 4; ++c) acc[r][c] = 0.f;
    }

    for (int kt = 0; kt <= qt; ++kt) {
        __syncthreads();   // previous V reads done before overwrite
        // load K tile (pre-scaled by ATTN_SCALE/sqrt(key_self))
        {
            int r  = tid >> 4;
            int c4 = (tid & 15) * 4;
#pragma unroll
            for (int it = 0; it < 4; ++it) {
                int row = r + it * 16;
                float4 v = *(const float4*)&g_K[(size_t)(kt * 64 + row) * DMODEL + kvh * DH + c4];
                KVs[row * LDP + c4 + 0] = v.x;
                KVs[row * LDP + c4 + 1] = v.y;
                KVs[row * LDP + c4 + 2] = v.z;
                KVs[row * LDP + c4 + 3] = v.w;
            }
        }
        __syncthreads();

        // scores for this 64x64 tile (4x4 per thread)
        float sfr[4][4];
#pragma unroll
        for (int r = 0; r < 4; ++r)
#pragma unroll
            for (int c = 0; c < 4; ++c) sfr[r][c] = 0.f;

#pragma unroll 8
        for (int d = 0; d < 64; ++d) {
            float qf[4], kf[4];
#pragma unroll
            for (int r = 0; r < 4; ++r) qf[r] = Qs[(ty * 4 + r) * LDP + d];
#pragma unroll
            for (int c = 0; c < 4; ++c) kf[c] = KVs[(tx * 4 + c) * LDP + d];
#pragma unroll
            for (int r = 0; r < 4; ++r)
#pragma unroll
                for (int c = 0; c < 4; ++c)
                    sfr[r][c] = fmaf(qf[r], kf[c], sfr[r][c]);
        }
        __syncthreads();   // done reading K; safe to overwrite with V

        // load V tile into same buffer
        {
            int r  = tid >> 4;
            int c4 = (tid & 15) * 4;
#pragma unroll
            for (int it = 0; it < 4; ++it) {
                int row = r + it * 16;
                float4 v = *(const float4*)&g_V[(size_t)(kt * 64 + row) * DMODEL + kvh * DH + c4];
                KVs[row * LDP + c4 + 0] = v.x;
                KVs[row * LDP + c4 + 1] = v.y;
                KVs[row * LDP + c4 + 2] = v.z;
                KVs[row * LDP + c4 + 3] = v.w;
            }
        }

        // activation + sink threshold -> Ws
        bool diag = (kt == qt);
#pragma unroll
        for (int r = 0; r < 4; ++r) {
            int i = ty * 4 + r;
#pragma unroll
            for (int c = 0; c < 4; ++c) {
                int j = tx * 4 + c;
                float w = 0.f;
                if (!diag || j <= i) {
                    float x  = sfr[r][c];
                    float sp = fmaxf(x, 0.f) + log1pf(expf(-fabsf(x)));
                    float sg = 1.0f / (1.0f + expf(-SILU_SCALE * sp));
                    w = sp * sg;
                    if (w < sink) w = 0.f;
                    else          rsum[r] += w;
                }
                Ws[i * LDP + j] = w;
            }
        }
        __syncthreads();   // V loaded + Ws written

        // acc += Ws @ V
#pragma unroll 8
        for (int j = 0; j < 64; ++j) {
            float wf[4], vf[4];
#pragma unroll
            for (int r = 0; r < 4; ++r) wf[r] = Ws[(ty * 4 + r) * LDP + j];
#pragma unroll
            for (int c = 0; c < 4; ++c) vf[c] = KVs[j * LDP + tx * 4 + c];
#pragma unroll
            for (int r = 0; r < 4; ++r)
#pragma unroll
                for (int c = 0; c < 4; ++c)
                    acc[r][c] = fmaf(wf[r], vf[c], acc[r][c]);
        }
    }

    __syncthreads();
    // reduce row-sums across the 16 tx threads (reuse Ws as scratch)
    float* RS = Ws;
#pragma unroll
    for (int r = 0; r < 4; ++r) RS[(ty * 4 + r) * 16 + tx] = rsum[r];
    __syncthreads();
    float* Tot = KVs;   // reuse
    if (tid < 64) {
        float s = 0.f;
#pragma unroll
        for (int x = 0; x < 16; ++x) s += RS[tid * 16 + x];
        Tot[tid] = s + sink + 1e-6f;
    }
    __syncthreads();

#pragma unroll
    for (int r = 0; r < 4; ++r) {
        int i = ty * 4 + r;
        float invT = 1.0f / Tot[i];
        int trow = qt * 64 + i;
#pragma unroll
        for (int c = 0; c < 4; ++c) {
            int dcol = tx * 4 + c;
            float vn = v_nulls[head * DH + dcol];
            g_OUT[(size_t)trow * QDIM + head * DH + dcol] = (acc[r][c] + sink * vn) * invT;
        }
    }
}

// ---------------------------------------------------------------------------
// Final reduce: Y = 0.25 * (sum of 4 K-split partials) + 0.25 * sum_br bias
// ---------------------------------------------------------------------------
__global__ __launch_bounds__(256)
void reduce_out_kernel(const float* __restrict__ part, const float* __restrict__ wob,
                       float* __restrict__ out)
{
    int idx = blockIdx.x * 256 + threadIdx.x;   // 0 .. 1048575
    int d = idx & (DMODEL - 1);
    float s = part[idx] + part[idx + 1048576] + part[idx + 2097152] + part[idx + 3145728];
    float b = wob[d] + wob[DMODEL + d] + wob[2 * DMODEL + d] + wob[3 * DMODEL + d];
    out[idx] = 0.25f * (s + b);
}

// ---------------------------------------------------------------------------
extern "C" void kernel_launch(void* const* d_in, const int* in_sizes, int n_in,
                              void* d_out, int out_size)
{
    const float* X        = (const float*)d_in[0];
    const float* W_Q      = (const float*)d_in[1];
    const float* b_Q      = (const float*)d_in[2];
    const float* W_K      = (const float*)d_in[3];
    const float* b_K      = (const float*)d_in[4];
    const float* W_V      = (const float*)d_in[5];
    const float* b_V      = (const float*)d_in[6];
    const float* sinks    = (const float*)d_in[7];
    const float* v_nulls  = (const float*)d_in[8];
    const float* W_O      = (const float*)d_in[9];   // (4,1024,1024) == (4096,1024)
    const float* W_O_bias = (const float*)d_in[10];  // (4,1024)
    float* out = (float*)d_out;

    float *Qp, *Kp, *Vp, *OUTp, *PARTp;
    cudaGetSymbolAddress((void**)&Qp,    g_Q);
    cudaGetSymbolAddress((void**)&Kp,    g_K);
    cudaGetSymbolAddress((void**)&Vp,    g_V);
    cudaGetSymbolAddress((void**)&OUTp,  g_OUT);
    cudaGetSymbolAddress((void**)&PARTp, g_part);

    dim3 blk(256);

    // Q projection: (1024x1024)@(1024x4096)+b
    sgemm_bias_kernel<<<dim3(32, 8, 1), blk>>>(X, W_Q, nullptr, b_Q, nullptr,
                                               Qp, nullptr, T_LEN, QDIM, DMODEL);
    // K and V projections in one launch via z
    sgemm_bias_kernel<<<dim3(8, 8, 2), blk>>>(X, W_K, W_V, b_K, b_V,
                                              Kp, Vp, T_LEN, DMODEL, DMODEL);
    // RoPE + key_self folding (1024 * 80 warps)
    rope_kernel<<<10240, 256>>>(Qp, Kp);

    // attention: 64 heads x 16 query tiles
    static const int ATTN_SMEM = 3 * 64 * LDP * (int)sizeof(float);  // 49920 B
    cudaFuncSetAttribute(attn_kernel, cudaFuncAttributeMaxDynamicSharedMemorySize, ATTN_SMEM);
    attn_kernel<<<dim3(16, 64), blk, ATTN_SMEM>>>(sinks, v_nulls);

    // output projection: OUT(1024x4096)@W_O(4096x1024), split-K=4
    sgemm_splitk_kernel<<<dim3(8, 8, 4), blk>>>(OUTp, W_O, PARTp,
                                                T_LEN, DMODEL, QDIM, 1024);
    reduce_out_kernel<<<4096, 256>>>(PARTp, W_O_bias, out);
}

// round 3
// speedup vs baseline: 1.5868x; 1.5868x over previous
#include <cuda_runtime.h>
#include <math.h>
#include <stdint.h>

#define T_LEN   1024
#define DMODEL  1024
#define QDIM    4096
#define HQ      64
#define HK      16
#define DH      64
#define SILU_SCALE 1.8137993642342178f   /* pi / sqrt(3) */
#define ATTN_SCALE 0.125f                /* DH^-0.5 */

static __device__ float g_Q[T_LEN * QDIM];
static __device__ float g_K[T_LEN * DMODEL];
static __device__ float g_V[T_LEN * DMODEL];
static __device__ float g_OUT[T_LEN * QDIM];
static __device__ float g_part[4 * T_LEN * DMODEL];

// ===========================================================================
// fast-math helpers (explicit PTX, independent of -use_fast_math)
// ===========================================================================
__device__ __forceinline__ float f_ex2(float x) { float y; asm("ex2.approx.ftz.f32 %0,%1;" : "=f"(y) : "f"(x)); return y; }
__device__ __forceinline__ float f_lg2(float x) { float y; asm("lg2.approx.ftz.f32 %0,%1;" : "=f"(y) : "f"(x)); return y; }
__device__ __forceinline__ float f_rcp(float x) { float y; asm("rcp.approx.ftz.f32 %0,%1;" : "=f"(y) : "f"(x)); return y; }
__device__ __forceinline__ uint32_t f2tf(float x) { uint32_t r; asm("cvt.rna.tf32.f32 %0,%1;" : "=r"(r) : "f"(x)); return r; }

// m16n8k8 tf32 HMMA (sm_80+, valid on compute_103 base target)
__device__ __forceinline__ void mma_tf32(float* d, const uint32_t* a, const uint32_t* b) {
    asm volatile(
        "mma.sync.aligned.m16n8k8.row.col.f32.tf32.tf32.f32 "
        "{%0,%1,%2,%3}, {%4,%5,%6,%7}, {%8,%9}, {%0,%1,%2,%3};"
        : "+f"(d[0]), "+f"(d[1]), "+f"(d[2]), "+f"(d[3])
        : "r"(a[0]), "r"(a[1]), "r"(a[2]), "r"(a[3]), "r"(b[0]), "r"(b[1]));
}

// ===========================================================================
// tf32 tensor-core GEMM: 128x128 block tile, BK=32, 256 threads, 8 warps
// arranged 4(m) x 2(n); each warp computes 32x64 via 2x8 m16n8k8 fragments.
// SMEM pitches chosen so all fragment LDS are bank-conflict-free:
//   As[128][36]: frag bank = (4*row + col) % 32, row=g(8 vals), col=tg(4) -> distinct
//   Bs[32][136]: frag bank = (8*(tg+f) + g) % 32 -> distinct
// ===========================================================================
#define AS_PITCH 36
#define BS_PITCH 136
#define AS_WORDS (128 * AS_PITCH)
#define BS_WORDS (32 * BS_PITCH)
#define GEMM_SMEM_BYTES ((2 * AS_WORDS + 2 * BS_WORDS) * 4)

template <bool BIAS>
__device__ __forceinline__ void gemm_body(
    const float* __restrict__ A, const float* __restrict__ W,
    const float* __restrict__ bias, float* __restrict__ C,
    int lda, int N, int m0, int n0, int kbase, int kLen)
{
    extern __shared__ uint32_t sm[];
    uint32_t* AsBuf[2] = { sm, sm + AS_WORDS };
    uint32_t* BsBuf[2] = { sm + 2 * AS_WORDS, sm + 2 * AS_WORDS + BS_WORDS };

    int tid  = threadIdx.x;
    int lane = tid & 31, wid = tid >> 5;
    int wm = wid & 3, wn = wid >> 2;
    int g = lane >> 2, tg = lane & 3;

    float acc[2][8][4];
#pragma unroll
    for (int mf = 0; mf < 2; ++mf)
#pragma unroll
        for (int nf = 0; nf < 8; ++nf)
#pragma unroll
            for (int q = 0; q < 4; ++q) acc[mf][nf][q] = 0.f;

    float4 pa[4], pb[4];
    int arow = tid >> 3, aqc = tid & 7;     // A: rows arow+32i, cols 4*aqc
    int brow = tid >> 5, bnq = tid & 31;    // B: rows brow+8i,  cols 4*bnq

#define LD_TILE(k0)                                                             \
    do {                                                                        \
        _Pragma("unroll")                                                       \
        for (int i = 0; i < 4; ++i)                                             \
            pa[i] = *(const float4*)&A[(size_t)(m0 + arow + 32 * i) * lda + (k0) + 4 * aqc]; \
        _Pragma("unroll")                                                       \
        for (int i = 0; i < 4; ++i)                                             \
            pb[i] = *(const float4*)&W[(size_t)((k0) + brow + 8 * i) * N + n0 + 4 * bnq];    \
    } while (0)

#define ST_TILE(buf)                                                            \
    do {                                                                        \
        _Pragma("unroll")                                                       \
        for (int i = 0; i < 4; ++i) {                                           \
            uint32_t* p = &AsBuf[buf][(arow + 32 * i) * AS_PITCH + 4 * aqc];    \
            p[0] = f2tf(pa[i].x); p[1] = f2tf(pa[i].y);                         \
            p[2] = f2tf(pa[i].z); p[3] = f2tf(pa[i].w);                         \
        }                                                                       \
        _Pragma("unroll")                                                       \
        for (int i = 0; i < 4; ++i) {                                           \
            uint32_t* p = &BsBuf[buf][(brow + 8 * i) * BS_PITCH + 4 * bnq];     \
            p[0] = f2tf(pb[i].x); p[1] = f2tf(pb[i].y);                         \
            p[2] = f2tf(pb[i].z); p[3] = f2tf(pb[i].w);                         \
        }                                                                       \
    } while (0)

    LD_TILE(kbase);
    ST_TILE(0);
    __syncthreads();

    int NIT = kLen / 32;
    for (int it = 0; it < NIT; ++it) {
        int buf = it & 1;
        if (it + 1 < NIT) LD_TILE(kbase + (it + 1) * 32);

        const uint32_t* As = AsBuf[buf];
        const uint32_t* Bs = BsBuf[buf];
#pragma unroll
        for (int ks = 0; ks < 4; ++ks) {
            uint32_t af[2][4], bf[8][2];
#pragma unroll
            for (int mf = 0; mf < 2; ++mf) {
                const uint32_t* p = &As[(wm * 32 + mf * 16 + g) * AS_PITCH + ks * 8 + tg];
                af[mf][0] = p[0];
                af[mf][1] = p[8 * AS_PITCH];
                af[mf][2] = p[4];
                af[mf][3] = p[8 * AS_PITCH + 4];
            }
#pragma unroll
            for (int nf = 0; nf < 8; ++nf) {
                const uint32_t* p = &Bs[(ks * 8 + tg) * BS_PITCH + wn * 64 + nf * 8 + g];
                bf[nf][0] = p[0];
                bf[nf][1] = p[4 * BS_PITCH];
            }
#pragma unroll
            for (int mf = 0; mf < 2; ++mf)
#pragma unroll
                for (int nf = 0; nf < 8; ++nf)
                    mma_tf32(acc[mf][nf], af[mf], bf[nf]);
        }
        if (it + 1 < NIT) ST_TILE(buf ^ 1);
        __syncthreads();
    }

    // epilogue: D frag thread holds (row g, cols 2tg..2tg+1) and (row g+8, same)
#pragma unroll
    for (int mf = 0; mf < 2; ++mf) {
        int r0 = m0 + wm * 32 + mf * 16 + g;
#pragma unroll
        for (int nf = 0; nf < 8; ++nf) {
            int c = n0 + wn * 64 + nf * 8 + 2 * tg;
            float b0 = 0.f, b1 = 0.f;
            if (BIAS) { b0 = bias[c]; b1 = bias[c + 1]; }
            float2 v0 = { acc[mf][nf][0] + b0, acc[mf][nf][1] + b1 };
            float2 v1 = { acc[mf][nf][2] + b0, acc[mf][nf][3] + b1 };
            *(float2*)&C[(size_t)r0 * N + c]       = v0;
            *(float2*)&C[(size_t)(r0 + 8) * N + c] = v1;
        }
    }
#undef LD_TILE
#undef ST_TILE
}

__global__ __launch_bounds__(256)
void gemm_tc_bias(const float* __restrict__ A,
                  const float* __restrict__ W0, const float* __restrict__ W1,
                  const float* __restrict__ bias0, const float* __restrict__ bias1,
                  float* __restrict__ C0, float* __restrict__ C1,
                  int N, int K)
{
    const float* W    = blockIdx.z ? W1 : W0;
    const float* bias = blockIdx.z ? bias1 : bias0;
    float*       C    = blockIdx.z ? C1 : C0;
    gemm_body<true>(A, W, bias, C, K, N, blockIdx.y * 128, blockIdx.x * 128, 0, K);
}

__global__ __launch_bounds__(256)
void gemm_tc_splitk(const float* __restrict__ A, const float* __restrict__ W,
                    float* __restrict__ Cpart, int N, int lda, int kPer)
{
    int z = blockIdx.z;
    gemm_body<false>(A, W, nullptr, Cpart + (size_t)z * T_LEN * DMODEL,
                     lda, N, blockIdx.y * 128, blockIdx.x * 128, z * kPer, kPer);
}

// ---------------------------------------------------------------------------
// RoPE (in place) + key_self/ATTN_SCALE folding into K rows.
// ---------------------------------------------------------------------------
__global__ __launch_bounds__(256)
void rope_kernel(float* __restrict__ Q, float* __restrict__ K)
{
    int gw   = blockIdx.x * 8 + (threadIdx.x >> 5);
    int lane = threadIdx.x & 31;
    int slot = gw % (HQ + HK);
    int t    = gw / (HQ + HK);

    bool isK = (slot >= HQ);
    float* ptr = isK ? (K + (size_t)t * DMODEL + (slot - HQ) * DH)
                     : (Q + (size_t)t * QDIM + slot * DH);

    float x1 = ptr[2 * lane];
    float x2 = ptr[2 * lane + 1];

    float inv = 1.0f / powf(10000.0f, (float)(2 * lane) / 64.0f);
    float fr  = (float)t * inv;
    float s, c;
    sincosf(fr, &s, &c);

    float o1 = x1 * c - x2 * s;
    float o2 = x1 * s + x2 * c;

    if (isK) {
        float nrm = x1 * x1 + x2 * x2;   // rotation preserves pair norms
#pragma unroll
        for (int off = 16; off; off >>= 1)
            nrm += __shfl_xor_sync(0xffffffffu, nrm, off);
        float ks  = fmaxf(nrm, 1e-6f);
        float scl = ATTN_SCALE * rsqrtf(ks);
        o1 *= scl;
        o2 *= scl;
    }
    __syncwarp();
    ptr[lane]      = o1;
    ptr[lane + 32] = o2;
}

// ---------------------------------------------------------------------------
// Attention: fp32 CUDA cores, fast activation, heavy-tile-first scheduling.
// ---------------------------------------------------------------------------
#define LDP 65
__global__ __launch_bounds__(256)
void attn_kernel(const float* __restrict__ sinks, const float* __restrict__ v_nulls)
{
    extern __shared__ float smf[];
    float* Qs  = smf;
    float* KVs = Qs + 64 * LDP;
    float* Ws  = KVs + 64 * LDP;

    int head = blockIdx.y;
    int qt   = (gridDim.x - 1) - blockIdx.x;   // heavy tiles first
    int kvh  = head & (HK - 1);
    int tid  = threadIdx.x;
    int tx   = tid & 15;
    int ty   = tid >> 4;
    float sink = sinks[head];

    {
        int r  = tid >> 4;
        int c4 = (tid & 15) * 4;
#pragma unroll
        for (int it = 0; it < 4; ++it) {
            int row = r + it * 16;
            float4 v = *(const float4*)&g_Q[(size_t)(qt * 64 + row) * QDIM + head * DH + c4];
            Qs[row * LDP + c4 + 0] = v.x; Qs[row * LDP + c4 + 1] = v.y;
            Qs[row * LDP + c4 + 2] = v.z; Qs[row * LDP + c4 + 3] = v.w;
        }
    }

    float acc[4][4];
    float rsum[4];
#pragma unroll
    for (int r = 0; r < 4; ++r) {
        rsum[r] = 0.f;
#pragma unroll
        for (int c = 0; c < 4; ++c) acc[r][c] = 0.f;
    }

    for (int kt = 0; kt <= qt; ++kt) {
        __syncthreads();
        {
            int r  = tid >> 4;
            int c4 = (tid & 15) * 4;
#pragma unroll
            for (int it = 0; it < 4; ++it) {
                int row = r + it * 16;
                float4 v = *(const float4*)&g_K[(size_t)(kt * 64 + row) * DMODEL + kvh * DH + c4];
                KVs[row * LDP + c4 + 0] = v.x; KVs[row * LDP + c4 + 1] = v.y;
                KVs[row * LDP + c4 + 2] = v.z; KVs[row * LDP + c4 + 3] = v.w;
            }
        }
        __syncthreads();

        float sfr[4][4];
#pragma unroll
        for (int r = 0; r < 4; ++r)
#pragma unroll
            for (int c = 0; c < 4; ++c) sfr[r][c] = 0.f;

#pragma unroll 8
        for (int d = 0; d < 64; ++d) {
            float qf[4], kf[4];
#pragma unroll
            for (int r = 0; r < 4; ++r) qf[r] = Qs[(ty * 4 + r) * LDP + d];
#pragma unroll
            for (int c = 0; c < 4; ++c) kf[c] = KVs[(tx * 4 + c) * LDP + d];
#pragma unroll
            for (int r = 0; r < 4; ++r)
#pragma unroll
                for (int c = 0; c < 4; ++c)
                    sfr[r][c] = fmaf(qf[r], kf[c], sfr[r][c]);
        }
        __syncthreads();

        {
            int r  = tid >> 4;
            int c4 = (tid & 15) * 4;
#pragma unroll
            for (int it = 0; it < 4; ++it) {
                int row = r + it * 16;
                float4 v = *(const float4*)&g_V[(size_t)(kt * 64 + row) * DMODEL + kvh * DH + c4];
                KVs[row * LDP + c4 + 0] = v.x; KVs[row * LDP + c4 + 1] = v.y;
                KVs[row * LDP + c4 + 2] = v.z; KVs[row * LDP + c4 + 3] = v.w;
            }
        }

        // fast activation: u = log2(1+e^x); sp = ln2*u; gate = 1/(1+2^(-S*u))
        bool diag = (kt == qt);
#pragma unroll
        for (int r = 0; r < 4; ++r) {
            int i = ty * 4 + r;
#pragma unroll
            for (int c = 0; c < 4; ++c) {
                int j = tx * 4 + c;
                float w = 0.f;
                if (!diag || j <= i) {
                    float x = fminf(sfr[r][c], 60.f);
                    float t = f_ex2(x * 1.44269504f);
                    float u = f_lg2(1.0f + t);
                    w = 0.69314718f * u * f_rcp(1.0f + f_ex2(-SILU_SCALE * u));
                    if (w < sink) w = 0.f;
                    else          rsum[r] += w;
                }
                Ws[i * LDP + j] = w;
            }
        }
        __syncthreads();

#pragma unroll 8
        for (int j = 0; j < 64; ++j) {
            float wf[4], vf[4];
#pragma unroll
            for (int r = 0; r < 4; ++r) wf[r] = Ws[(ty * 4 + r) * LDP + j];
#pragma unroll
            for (int c = 0; c < 4; ++c) vf[c] = KVs[j * LDP + tx * 4 + c];
#pragma unroll
            for (int r = 0; r < 4; ++r)
#pragma unroll
                for (int c = 0; c < 4; ++c)
                    acc[r][c] = fmaf(wf[r], vf[c], acc[r][c]);
        }
    }

    __syncthreads();
    float* RS = Ws;
#pragma unroll
    for (int r = 0; r < 4; ++r) RS[(ty * 4 + r) * 16 + tx] = rsum[r];
    __syncthreads();
    float* Tot = KVs;
    if (tid < 64) {
        float s = 0.f;
#pragma unroll
        for (int x = 0; x < 16; ++x) s += RS[tid * 16 + x];
        Tot[tid] = s + sink + 1e-6f;
    }
    __syncthreads();

#pragma unroll
    for (int r = 0; r < 4; ++r) {
        int i = ty * 4 + r;
        float invT = 1.0f / Tot[i];
        int trow = qt * 64 + i;
#pragma unroll
        for (int c = 0; c < 4; ++c) {
            int dcol = tx * 4 + c;
            float vn = v_nulls[head * DH + dcol];
            g_OUT[(size_t)trow * QDIM + head * DH + dcol] = (acc[r][c] + sink * vn) * invT;
        }
    }
}

// ---------------------------------------------------------------------------
// Final reduce: Y = 0.25 * (sum of 4 K-split partials + sum_br bias)
// ---------------------------------------------------------------------------
__global__ __launch_bounds__(256)
void reduce_out_kernel(const float* __restrict__ part, const float* __restrict__ wob,
                       float* __restrict__ out)
{
    int idx = blockIdx.x * 256 + threadIdx.x;
    int d = idx & (DMODEL - 1);
    float s = part[idx] + part[idx + 1048576] + part[idx + 2097152] + part[idx + 3145728];
    float b = wob[d] + wob[DMODEL + d] + wob[2 * DMODEL + d] + wob[3 * DMODEL + d];
    out[idx] = 0.25f * (s + b);
}

// ---------------------------------------------------------------------------
extern "C" void kernel_launch(void* const* d_in, const int* in_sizes, int n_in,
                              void* d_out, int out_size)
{
    const float* X        = (const float*)d_in[0];
    const float* W_Q      = (const float*)d_in[1];
    const float* b_Q      = (const float*)d_in[2];
    const float* W_K      = (const float*)d_in[3];
    const float* b_K      = (const float*)d_in[4];
    const float* W_V      = (const float*)d_in[5];
    const float* b_V      = (const float*)d_in[6];
    const float* sinks    = (const float*)d_in[7];
    const float* v_nulls  = (const float*)d_in[8];
    const float* W_O      = (const float*)d_in[9];   // (4,1024,1024) == (4096,1024)
    const float* W_O_bias = (const float*)d_in[10];  // (4,1024)
    float* out = (float*)d_out;

    float *Qp, *Kp, *Vp, *OUTp, *PARTp;
    cudaGetSymbolAddress((void**)&Qp,    g_Q);
    cudaGetSymbolAddress((void**)&Kp,    g_K);
    cudaGetSymbolAddress((void**)&Vp,    g_V);
    cudaGetSymbolAddress((void**)&OUTp,  g_OUT);
    cudaGetSymbolAddress((void**)&PARTp, g_part);

    cudaFuncSetAttribute(gemm_tc_bias, cudaFuncAttributeMaxDynamicSharedMemorySize, GEMM_SMEM_BYTES);
    cudaFuncSetAttribute(gemm_tc_splitk, cudaFuncAttributeMaxDynamicSharedMemorySize, GEMM_SMEM_BYTES);
    cudaFuncSetAttribute(attn_kernel, cudaFuncAttributeMaxDynamicSharedMemorySize, 3 * 64 * LDP * (int)sizeof(float));

    // Q projection: X(1024x1024) @ W_Q(1024x4096) + b_Q
    gemm_tc_bias<<<dim3(QDIM / 128, T_LEN / 128, 1), 256, GEMM_SMEM_BYTES>>>(
        X, W_Q, W_Q, b_Q, b_Q, Qp, Qp, QDIM, DMODEL);
    // K and V projections share one launch via z
    gemm_tc_bias<<<dim3(DMODEL / 128, T_LEN / 128, 2), 256, GEMM_SMEM_BYTES>>>(
        X, W_K, W_V, b_K, b_V, Kp, Vp, DMODEL, DMODEL);
    // RoPE + key_self folding
    rope_kernel<<<10240, 256>>>(Qp, Kp);
    // attention: 64 heads x 16 query tiles
    attn_kernel<<<dim3(16, 64), 256, 3 * 64 * LDP * (int)sizeof(float)>>>(sinks, v_nulls);
    // output projection: OUT(1024x4096) @ W_O(4096x1024), split-K=4
    gemm_tc_splitk<<<dim3(DMODEL / 128, T_LEN / 128, 4), 256, GEMM_SMEM_BYTES>>>(
        OUTp, W_O, PARTp, DMODEL, QDIM, 1024);
    reduce_out_kernel<<<4096, 256>>>(PARTp, W_O_bias, out);
}

// round 4
// speedup vs baseline: 2.3276x; 1.4669x over previous
#include <cuda_runtime.h>
#include <math.h>
#include <stdint.h>

#define T_LEN   1024
#define DMODEL  1024
#define QDIM    4096
#define HQ      64
#define HK      16
#define DH      64
#define SILU_SCALE 1.8137993642342178f   /* pi / sqrt(3) */
#define ATTN_SCALE 0.125f                /* DH^-0.5 */

static __device__ float g_Q[T_LEN * QDIM];
static __device__ float g_K[T_LEN * DMODEL];
static __device__ float g_V[T_LEN * DMODEL];
static __device__ float g_OUT[T_LEN * QDIM];
static __device__ float g_part[4 * T_LEN * DMODEL];

// ===========================================================================
// fast-math + mma helpers
// ===========================================================================
__device__ __forceinline__ float f_ex2(float x) { float y; asm("ex2.approx.ftz.f32 %0,%1;" : "=f"(y) : "f"(x)); return y; }
__device__ __forceinline__ float f_lg2(float x) { float y; asm("lg2.approx.ftz.f32 %0,%1;" : "=f"(y) : "f"(x)); return y; }
__device__ __forceinline__ float f_rcp(float x) { float y; asm("rcp.approx.ftz.f32 %0,%1;" : "=f"(y) : "f"(x)); return y; }
__device__ __forceinline__ uint32_t f2tf(float x) { uint32_t r; asm("cvt.rna.tf32.f32 %0,%1;" : "=r"(r) : "f"(x)); return r; }

__device__ __forceinline__ void mma_tf32(float* d, const uint32_t* a, const uint32_t* b) {
    asm volatile(
        "mma.sync.aligned.m16n8k8.row.col.f32.tf32.tf32.f32 "
        "{%0,%1,%2,%3}, {%4,%5,%6,%7}, {%8,%9}, {%0,%1,%2,%3};"
        : "+f"(d[0]), "+f"(d[1]), "+f"(d[2]), "+f"(d[3])
        : "r"(a[0]), "r"(a[1]), "r"(a[2]), "r"(a[3]), "r"(b[0]), "r"(b[1]));
}

// ===========================================================================
// Dense tf32 GEMM (unchanged from R3): 128x128 tile, BK=32, 8 warps.
// ===========================================================================
#define AS_PITCH 36
#define BS_PITCH 136
#define AS_WORDS (128 * AS_PITCH)
#define BS_WORDS (32 * BS_PITCH)
#define GEMM_SMEM_BYTES ((2 * AS_WORDS + 2 * BS_WORDS) * 4)

template <bool BIAS>
__device__ __forceinline__ void gemm_body(
    const float* __restrict__ A, const float* __restrict__ W,
    const float* __restrict__ bias, float* __restrict__ C,
    int lda, int N, int m0, int n0, int kbase, int kLen)
{
    extern __shared__ uint32_t sm[];
    uint32_t* AsBuf[2] = { sm, sm + AS_WORDS };
    uint32_t* BsBuf[2] = { sm + 2 * AS_WORDS, sm + 2 * AS_WORDS + BS_WORDS };

    int tid  = threadIdx.x;
    int lane = tid & 31, wid = tid >> 5;
    int wm = wid & 3, wn = wid >> 2;
    int g = lane >> 2, tg = lane & 3;

    float acc[2][8][4];
#pragma unroll
    for (int mf = 0; mf < 2; ++mf)
#pragma unroll
        for (int nf = 0; nf < 8; ++nf)
#pragma unroll
            for (int q = 0; q < 4; ++q) acc[mf][nf][q] = 0.f;

    float4 pa[4], pb[4];
    int arow = tid >> 3, aqc = tid & 7;
    int brow = tid >> 5, bnq = tid & 31;

#define LD_TILE(k0)                                                             \
    do {                                                                        \
        _Pragma("unroll")                                                       \
        for (int i = 0; i < 4; ++i)                                             \
            pa[i] = *(const float4*)&A[(size_t)(m0 + arow + 32 * i) * lda + (k0) + 4 * aqc]; \
        _Pragma("unroll")                                                       \
        for (int i = 0; i < 4; ++i)                                             \
            pb[i] = *(const float4*)&W[(size_t)((k0) + brow + 8 * i) * N + n0 + 4 * bnq];    \
    } while (0)

#define ST_TILE(buf)                                                            \
    do {                                                                        \
        _Pragma("unroll")                                                       \
        for (int i = 0; i < 4; ++i) {                                           \
            uint32_t* p = &AsBuf[buf][(arow + 32 * i) * AS_PITCH + 4 * aqc];    \
            p[0] = f2tf(pa[i].x); p[1] = f2tf(pa[i].y);                         \
            p[2] = f2tf(pa[i].z); p[3] = f2tf(pa[i].w);                         \
        }                                                                       \
        _Pragma("unroll")                                                       \
        for (int i = 0; i < 4; ++i) {                                           \
            uint32_t* p = &BsBuf[buf][(brow + 8 * i) * BS_PITCH + 4 * bnq];     \
            p[0] = f2tf(pb[i].x); p[1] = f2tf(pb[i].y);                         \
            p[2] = f2tf(pb[i].z); p[3] = f2tf(pb[i].w);                         \
        }                                                                       \
    } while (0)

    LD_TILE(kbase);
    ST_TILE(0);
    __syncthreads();

    int NIT = kLen / 32;
    for (int it = 0; it < NIT; ++it) {
        int buf = it & 1;
        if (it + 1 < NIT) LD_TILE(kbase + (it + 1) * 32);

        const uint32_t* As = AsBuf[buf];
        const uint32_t* Bs = BsBuf[buf];
#pragma unroll
        for (int ks = 0; ks < 4; ++ks) {
            uint32_t af[2][4], bf[8][2];
#pragma unroll
            for (int mf = 0; mf < 2; ++mf) {
                const uint32_t* p = &As[(wm * 32 + mf * 16 + g) * AS_PITCH + ks * 8 + tg];
                af[mf][0] = p[0];
                af[mf][1] = p[8 * AS_PITCH];
                af[mf][2] = p[4];
                af[mf][3] = p[8 * AS_PITCH + 4];
            }
#pragma unroll
            for (int nf = 0; nf < 8; ++nf) {
                const uint32_t* p = &Bs[(ks * 8 + tg) * BS_PITCH + wn * 64 + nf * 8 + g];
                bf[nf][0] = p[0];
                bf[nf][1] = p[4 * BS_PITCH];
            }
#pragma unroll
            for (int mf = 0; mf < 2; ++mf)
#pragma unroll
                for (int nf = 0; nf < 8; ++nf)
                    mma_tf32(acc[mf][nf], af[mf], bf[nf]);
        }
        if (it + 1 < NIT) ST_TILE(buf ^ 1);
        __syncthreads();
    }

#pragma unroll
    for (int mf = 0; mf < 2; ++mf) {
        int r0 = m0 + wm * 32 + mf * 16 + g;
#pragma unroll
        for (int nf = 0; nf < 8; ++nf) {
            int c = n0 + wn * 64 + nf * 8 + 2 * tg;
            float b0 = 0.f, b1 = 0.f;
            if (BIAS) { b0 = bias[c]; b1 = bias[c + 1]; }
            float2 v0 = { acc[mf][nf][0] + b0, acc[mf][nf][1] + b1 };
            float2 v1 = { acc[mf][nf][2] + b0, acc[mf][nf][3] + b1 };
            *(float2*)&C[(size_t)r0 * N + c]       = v0;
            *(float2*)&C[(size_t)(r0 + 8) * N + c] = v1;
        }
    }
#undef LD_TILE
#undef ST_TILE
}

__global__ __launch_bounds__(256)
void gemm_tc_bias(const float* __restrict__ A,
                  const float* __restrict__ W0, const float* __restrict__ W1,
                  const float* __restrict__ bias0, const float* __restrict__ bias1,
                  float* __restrict__ C0, float* __restrict__ C1,
                  int N, int K)
{
    const float* W    = blockIdx.z ? W1 : W0;
    const float* bias = blockIdx.z ? bias1 : bias0;
    float*       C    = blockIdx.z ? C1 : C0;
    gemm_body<true>(A, W, bias, C, K, N, blockIdx.y * 128, blockIdx.x * 128, 0, K);
}

__global__ __launch_bounds__(256)
void gemm_tc_splitk(const float* __restrict__ A, const float* __restrict__ W,
                    float* __restrict__ Cpart, int N, int lda, int kPer)
{
    int z = blockIdx.z;
    gemm_body<false>(A, W, nullptr, Cpart + (size_t)z * T_LEN * DMODEL,
                     lda, N, blockIdx.y * 128, blockIdx.x * 128, z * kPer, kPer);
}

// ---------------------------------------------------------------------------
// RoPE (in place) + key_self/ATTN_SCALE folding into K rows.
// ---------------------------------------------------------------------------
__global__ __launch_bounds__(256)
void rope_kernel(float* __restrict__ Q, float* __restrict__ K)
{
    int gw   = blockIdx.x * 8 + (threadIdx.x >> 5);
    int lane = threadIdx.x & 31;
    int slot = gw % (HQ + HK);
    int t    = gw / (HQ + HK);

    bool isK = (slot >= HQ);
    float* ptr = isK ? (K + (size_t)t * DMODEL + (slot - HQ) * DH)
                     : (Q + (size_t)t * QDIM + slot * DH);

    float x1 = ptr[2 * lane];
    float x2 = ptr[2 * lane + 1];

    float inv = 1.0f / powf(10000.0f, (float)(2 * lane) / 64.0f);
    float fr  = (float)t * inv;
    float s, c;
    sincosf(fr, &s, &c);

    float o1 = x1 * c - x2 * s;
    float o2 = x1 * s + x2 * c;

    if (isK) {
        float nrm = x1 * x1 + x2 * x2;
#pragma unroll
        for (int off = 16; off; off >>= 1)
            nrm += __shfl_xor_sync(0xffffffffu, nrm, off);
        float ks  = fmaxf(nrm, 1e-6f);
        float scl = ATTN_SCALE * rsqrtf(ks);
        o1 *= scl;
        o2 *= scl;
    }
    __syncwarp();
    ptr[lane]      = o1;
    ptr[lane + 32] = o2;
}

// ===========================================================================
// Tensor-core attention. One block = (head, 64-query tile), 8 warps (4m x 2n).
// Scores S = Q @ K^T via m16n8k8 tf32 (B-frags straight from row-major K);
// activation in registers; activated W -> SMEM (tf32); V staged transposed;
// O += W @ V via mma. Row sums in registers, shfl+smem reduce at end.
// ===========================================================================
#define APITCH 68
#define ATTN_SMEM_BYTES ((3 * 64 * APITCH + 128 + 64) * 4)

__global__ __launch_bounds__(256)
void attn_tc_kernel(const float* __restrict__ sinks, const float* __restrict__ v_nulls)
{
    extern __shared__ uint32_t smu[];
    uint32_t* Qs  = smu;                    // 64 x APITCH (tf32)
    uint32_t* KVs = Qs + 64 * APITCH;       // K rows, then V^T
    uint32_t* Ws  = KVs + 64 * APITCH;      // activated weights (tf32)
    float* RSm = (float*)(Ws + 64 * APITCH);  // [8 warps][16 rows]
    float* Tot = RSm + 128;                   // [64]

    int head = blockIdx.y;
    int qt   = (gridDim.x - 1) - blockIdx.x;   // heavy tiles first
    int kvh  = head & (HK - 1);
    int tid  = threadIdx.x;
    int lane = tid & 31, wid = tid >> 5;
    int wm = wid & 3, wn = wid >> 2;
    int g = lane >> 2, tg = lane & 3;
    float sink = sinks[head];

    // load Q tile (tf32)
#pragma unroll
    for (int i = 0; i < 4; ++i) {
        int idx = tid + 256 * i;
        int r = idx >> 4, c = (idx & 15) * 4;
        float4 v = *(const float4*)&g_Q[(size_t)(qt * 64 + r) * QDIM + head * DH + c];
        uint32_t* p = &Qs[r * APITCH + c];
        p[0] = f2tf(v.x); p[1] = f2tf(v.y); p[2] = f2tf(v.z); p[3] = f2tf(v.w);
    }

    float oacc[4][4];
#pragma unroll
    for (int nf = 0; nf < 4; ++nf)
#pragma unroll
        for (int q = 0; q < 4; ++q) oacc[nf][q] = 0.f;
    float rs0 = 0.f, rs1 = 0.f;

    const uint32_t* aQbase = &Qs[(wm * 16 + g) * APITCH + tg];

    for (int kt = 0; kt <= qt; ++kt) {
        __syncthreads();   // prev iteration's W@V reads of KVs/Ws complete
        // ---- load K tile (rows = key, cols = dh), tf32
#pragma unroll
        for (int i = 0; i < 4; ++i) {
            int idx = tid + 256 * i;
            int r = idx >> 4, c = (idx & 15) * 4;
            float4 v = *(const float4*)&g_K[(size_t)(kt * 64 + r) * DMODEL + kvh * DH + c];
            uint32_t* p = &KVs[r * APITCH + c];
            p[0] = f2tf(v.x); p[1] = f2tf(v.y); p[2] = f2tf(v.z); p[3] = f2tf(v.w);
        }
        __syncthreads();

        // ---- scores: S = Q @ K^T
        float sacc[4][4];
#pragma unroll
        for (int nf = 0; nf < 4; ++nf)
#pragma unroll
            for (int q = 0; q < 4; ++q) sacc[nf][q] = 0.f;

#pragma unroll
        for (int ks = 0; ks < 8; ++ks) {
            uint32_t af[4], bf[4][2];
            const uint32_t* ap = aQbase + ks * 8;
            af[0] = ap[0]; af[1] = ap[8 * APITCH];
            af[2] = ap[4]; af[3] = ap[8 * APITCH + 4];
#pragma unroll
            for (int nf = 0; nf < 4; ++nf) {
                const uint32_t* bp = &KVs[(wn * 32 + nf * 8 + g) * APITCH + ks * 8 + tg];
                bf[nf][0] = bp[0]; bf[nf][1] = bp[4];
            }
#pragma unroll
            for (int nf = 0; nf < 4; ++nf)
                mma_tf32(sacc[nf], af, bf[nf]);
        }
        __syncthreads();   // done reading K from KVs

        // ---- load V transposed: KVs[d][j] = V[kt*64+j][kvh*64+d]
#pragma unroll
        for (int i = 0; i < 4; ++i) {
            int idx = tid + 256 * i;
            int j = idx >> 4, dc = (idx & 15) * 4;
            float4 v = *(const float4*)&g_V[(size_t)(kt * 64 + j) * DMODEL + kvh * DH + dc];
            KVs[(dc + 0) * APITCH + j] = f2tf(v.x);
            KVs[(dc + 1) * APITCH + j] = f2tf(v.y);
            KVs[(dc + 2) * APITCH + j] = f2tf(v.z);
            KVs[(dc + 3) * APITCH + j] = f2tf(v.w);
        }

        // ---- activation on score fragments (registers) -> Ws (tf32)
        bool diag = (kt == qt);
        int li0 = wm * 16 + g;       // local rows
        int gi0 = qt * 64 + li0;
#pragma unroll
        for (int nf = 0; nf < 4; ++nf) {
            int ljc = wn * 32 + nf * 8 + 2 * tg;
            int gj  = kt * 64 + ljc;
            float w[4];
#pragma unroll
            for (int q = 0; q < 4; ++q) {
                float x = fminf(sacc[nf][q], 60.f);
                float t = f_ex2(x * 1.44269504f);
                float u = f_lg2(1.0f + t);
                float ww = 0.69314718f * u * f_rcp(1.0f + f_ex2(-SILU_SCALE * u));
                int gi = gi0 + ((q >> 1) << 3);         // +8 for q=2,3
                int gjj = gj + (q & 1);
                if ((diag && gjj > gi) || ww < sink) ww = 0.f;
                w[q] = ww;
            }
            rs0 += w[0] + w[1];
            rs1 += w[2] + w[3];
            uint2 s0 = { f2tf(w[0]), f2tf(w[1]) };
            uint2 s1 = { f2tf(w[2]), f2tf(w[3]) };
            *(uint2*)&Ws[li0 * APITCH + ljc]       = s0;
            *(uint2*)&Ws[(li0 + 8) * APITCH + ljc] = s1;
        }
        __syncthreads();   // Vt + Ws ready

        // ---- O += W @ V   (A = Ws rows, B = Vt rows)
#pragma unroll
        for (int ks = 0; ks < 8; ++ks) {
            uint32_t af[4], bf[4][2];
            const uint32_t* ap = &Ws[(wm * 16 + g) * APITCH + ks * 8 + tg];
            af[0] = ap[0]; af[1] = ap[8 * APITCH];
            af[2] = ap[4]; af[3] = ap[8 * APITCH + 4];
#pragma unroll
            for (int nf = 0; nf < 4; ++nf) {
                const uint32_t* bp = &KVs[(wn * 32 + nf * 8 + g) * APITCH + ks * 8 + tg];
                bf[nf][0] = bp[0]; bf[nf][1] = bp[4];
            }
#pragma unroll
            for (int nf = 0; nf < 4; ++nf)
                mma_tf32(oacc[nf], af, bf[nf]);
        }
    }

    // ---- row-sum reduction
    __syncthreads();
    rs0 += __shfl_xor_sync(0xffffffffu, rs0, 1);
    rs0 += __shfl_xor_sync(0xffffffffu, rs0, 2);
    rs1 += __shfl_xor_sync(0xffffffffu, rs1, 1);
    rs1 += __shfl_xor_sync(0xffffffffu, rs1, 2);
    if (tg == 0) {
        RSm[wid * 16 + g]     = rs0;
        RSm[wid * 16 + 8 + g] = rs1;
    }
    __syncthreads();
    if (tid < 64)
        Tot[tid] = RSm[(tid >> 4) * 16 + (tid & 15)]
                 + RSm[((tid >> 4) + 4) * 16 + (tid & 15)] + sink + 1e-6f;
    __syncthreads();

    // ---- epilogue
    int li0 = wm * 16 + g;
    float invT0 = 1.0f / Tot[li0];
    float invT1 = 1.0f / Tot[li0 + 8];
#pragma unroll
    for (int nf = 0; nf < 4; ++nf) {
        int dloc = wn * 32 + nf * 8 + 2 * tg;
        float vn0 = v_nulls[head * DH + dloc];
        float vn1 = v_nulls[head * DH + dloc + 1];
        float2 o0 = { (oacc[nf][0] + sink * vn0) * invT0,
                      (oacc[nf][1] + sink * vn1) * invT0 };
        float2 o1 = { (oacc[nf][2] + sink * vn0) * invT1,
                      (oacc[nf][3] + sink * vn1) * invT1 };
        *(float2*)&g_OUT[(size_t)(qt * 64 + li0) * QDIM + head * DH + dloc]     = o0;
        *(float2*)&g_OUT[(size_t)(qt * 64 + li0 + 8) * QDIM + head * DH + dloc] = o1;
    }
}

// ---------------------------------------------------------------------------
// Final reduce: Y = 0.25 * (sum of 4 K-split partials + sum_br bias)
// ---------------------------------------------------------------------------
__global__ __launch_bounds__(256)
void reduce_out_kernel(const float* __restrict__ part, const float* __restrict__ wob,
                       float* __restrict__ out)
{
    int idx = blockIdx.x * 256 + threadIdx.x;
    int d = idx & (DMODEL - 1);
    float s = part[idx] + part[idx + 1048576] + part[idx + 2097152] + part[idx + 3145728];
    float b = wob[d] + wob[DMODEL + d] + wob[2 * DMODEL + d] + wob[3 * DMODEL + d];
    out[idx] = 0.25f * (s + b);
}

// ---------------------------------------------------------------------------
extern "C" void kernel_launch(void* const* d_in, const int* in_sizes, int n_in,
                              void* d_out, int out_size)
{
    const float* X        = (const float*)d_in[0];
    const float* W_Q      = (const float*)d_in[1];
    const float* b_Q      = (const float*)d_in[2];
    const float* W_K      = (const float*)d_in[3];
    const float* b_K      = (const float*)d_in[4];
    const float* W_V      = (const float*)d_in[5];
    const float* b_V      = (const float*)d_in[6];
    const float* sinks    = (const float*)d_in[7];
    const float* v_nulls  = (const float*)d_in[8];
    const float* W_O      = (const float*)d_in[9];
    const float* W_O_bias = (const float*)d_in[10];
    float* out = (float*)d_out;

    float *Qp, *Kp, *Vp, *OUTp, *PARTp;
    cudaGetSymbolAddress((void**)&Qp,    g_Q);
    cudaGetSymbolAddress((void**)&Kp,    g_K);
    cudaGetSymbolAddress((void**)&Vp,    g_V);
    cudaGetSymbolAddress((void**)&OUTp,  g_OUT);
    cudaGetSymbolAddress((void**)&PARTp, g_part);

    cudaFuncSetAttribute(gemm_tc_bias, cudaFuncAttributeMaxDynamicSharedMemorySize, GEMM_SMEM_BYTES);
    cudaFuncSetAttribute(gemm_tc_splitk, cudaFuncAttributeMaxDynamicSharedMemorySize, GEMM_SMEM_BYTES);
    cudaFuncSetAttribute(attn_tc_kernel, cudaFuncAttributeMaxDynamicSharedMemorySize, ATTN_SMEM_BYTES);

    // Q projection
    gemm_tc_bias<<<dim3(QDIM / 128, T_LEN / 128, 1), 256, GEMM_SMEM_BYTES>>>(
        X, W_Q, W_Q, b_Q, b_Q, Qp, Qp, QDIM, DMODEL);
    // K and V projections
    gemm_tc_bias<<<dim3(DMODEL / 128, T_LEN / 128, 2), 256, GEMM_SMEM_BYTES>>>(
        X, W_K, W_V, b_K, b_V, Kp, Vp, DMODEL, DMODEL);
    // RoPE + key_self folding
    rope_kernel<<<10240, 256>>>(Qp, Kp);
    // tensor-core attention
    attn_tc_kernel<<<dim3(16, 64), 256, ATTN_SMEM_BYTES>>>(sinks, v_nulls);
    // output projection, split-K=4
    gemm_tc_splitk<<<dim3(DMODEL / 128, T_LEN / 128, 4), 256, GEMM_SMEM_BYTES>>>(
        OUTp, W_O, PARTp, DMODEL, QDIM, 1024);
    reduce_out_kernel<<<4096, 256>>>(PARTp, W_O_bias, out);
}

// round 5
// speedup vs baseline: 2.4985x; 1.0734x over previous
#include <cuda_runtime.h>
#include <math.h>
#include <stdint.h>

#define T_LEN   1024
#define DMODEL  1024
#define QDIM    4096
#define HQ      64
#define HK      16
#define DH      64
#define SILU_SCALE 1.8137993642342178f   /* pi / sqrt(3) */
#define ATTN_SCALE 0.125f                /* DH^-0.5 */

static __device__ float g_Q[T_LEN * QDIM];
static __device__ float g_K[T_LEN * DMODEL];
static __device__ float g_Vt[DMODEL * T_LEN];   // V transposed: [d][t]
static __device__ float g_OUT[T_LEN * QDIM];
static __device__ float g_part[4 * T_LEN * DMODEL];

// ===========================================================================
// fast-math + mma helpers
// ===========================================================================
__device__ __forceinline__ float f_ex2(float x) { float y; asm("ex2.approx.ftz.f32 %0,%1;" : "=f"(y) : "f"(x)); return y; }
__device__ __forceinline__ float f_lg2(float x) { float y; asm("lg2.approx.ftz.f32 %0,%1;" : "=f"(y) : "f"(x)); return y; }
__device__ __forceinline__ float f_rcp(float x) { float y; asm("rcp.approx.ftz.f32 %0,%1;" : "=f"(y) : "f"(x)); return y; }
__device__ __forceinline__ uint32_t f2tf(float x) { uint32_t r; asm("cvt.rna.tf32.f32 %0,%1;" : "=r"(r) : "f"(x)); return r; }

__device__ __forceinline__ void mma_tf32(float* d, const uint32_t* a, const uint32_t* b) {
    asm volatile(
        "mma.sync.aligned.m16n8k8.row.col.f32.tf32.tf32.f32 "
        "{%0,%1,%2,%3}, {%4,%5,%6,%7}, {%8,%9}, {%0,%1,%2,%3};"
        : "+f"(d[0]), "+f"(d[1]), "+f"(d[2]), "+f"(d[3])
        : "r"(a[0]), "r"(a[1]), "r"(a[2]), "r"(a[3]), "r"(b[0]), "r"(b[1]));
}

// ===========================================================================
// Dense tf32 GEMM: 128x128 tile, BK=32, 8 warps (4m x 2n).
// TRANS_C1: blockIdx.z==1 output written transposed (for V^T).
// ===========================================================================
#define AS_PITCH 36
#define BS_PITCH 136
#define AS_WORDS (128 * AS_PITCH)
#define BS_WORDS (32 * BS_PITCH)
#define GEMM_SMEM_BYTES ((2 * AS_WORDS + 2 * BS_WORDS) * 4)

template <bool BIAS, bool TRANS>
__device__ __forceinline__ void gemm_body(
    const float* __restrict__ A, const float* __restrict__ W,
    const float* __restrict__ bias, float* __restrict__ C,
    int lda, int N, int m0, int n0, int kbase, int kLen)
{
    extern __shared__ uint32_t sm[];
    uint32_t* AsBuf[2] = { sm, sm + AS_WORDS };
    uint32_t* BsBuf[2] = { sm + 2 * AS_WORDS, sm + 2 * AS_WORDS + BS_WORDS };

    int tid  = threadIdx.x;
    int lane = tid & 31, wid = tid >> 5;
    int wm = wid & 3, wn = wid >> 2;
    int g = lane >> 2, tg = lane & 3;

    float acc[2][8][4];
#pragma unroll
    for (int mf = 0; mf < 2; ++mf)
#pragma unroll
        for (int nf = 0; nf < 8; ++nf)
#pragma unroll
            for (int q = 0; q < 4; ++q) acc[mf][nf][q] = 0.f;

    float4 pa[4], pb[4];
    int arow = tid >> 3, aqc = tid & 7;
    int brow = tid >> 5, bnq = tid & 31;

#define LD_TILE(k0)                                                             \
    do {                                                                        \
        _Pragma("unroll")                                                       \
        for (int i = 0; i < 4; ++i)                                             \
            pa[i] = *(const float4*)&A[(size_t)(m0 + arow + 32 * i) * lda + (k0) + 4 * aqc]; \
        _Pragma("unroll")                                                       \
        for (int i = 0; i < 4; ++i)                                             \
            pb[i] = *(const float4*)&W[(size_t)((k0) + brow + 8 * i) * N + n0 + 4 * bnq];    \
    } while (0)

#define ST_TILE(buf)                                                            \
    do {                                                                        \
        _Pragma("unroll")                                                       \
        for (int i = 0; i < 4; ++i) {                                           \
            uint32_t* p = &AsBuf[buf][(arow + 32 * i) * AS_PITCH + 4 * aqc];    \
            p[0] = f2tf(pa[i].x); p[1] = f2tf(pa[i].y);                         \
            p[2] = f2tf(pa[i].z); p[3] = f2tf(pa[i].w);                         \
        }                                                                       \
        _Pragma("unroll")                                                       \
        for (int i = 0; i < 4; ++i) {                                           \
            uint32_t* p = &BsBuf[buf][(brow + 8 * i) * BS_PITCH + 4 * bnq];     \
            p[0] = f2tf(pb[i].x); p[1] = f2tf(pb[i].y);                         \
            p[2] = f2tf(pb[i].z); p[3] = f2tf(pb[i].w);                         \
        }                                                                       \
    } while (0)

    LD_TILE(kbase);
    ST_TILE(0);
    __syncthreads();

    int NIT = kLen / 32;
    for (int it = 0; it < NIT; ++it) {
        int buf = it & 1;
        if (it + 1 < NIT) LD_TILE(kbase + (it + 1) * 32);

        const uint32_t* As = AsBuf[buf];
        const uint32_t* Bs = BsBuf[buf];
#pragma unroll
        for (int ks = 0; ks < 4; ++ks) {
            uint32_t af[2][4], bf[8][2];
#pragma unroll
            for (int mf = 0; mf < 2; ++mf) {
                const uint32_t* p = &As[(wm * 32 + mf * 16 + g) * AS_PITCH + ks * 8 + tg];
                af[mf][0] = p[0];
                af[mf][1] = p[8 * AS_PITCH];
                af[mf][2] = p[4];
                af[mf][3] = p[8 * AS_PITCH + 4];
            }
#pragma unroll
            for (int nf = 0; nf < 8; ++nf) {
                const uint32_t* p = &Bs[(ks * 8 + tg) * BS_PITCH + wn * 64 + nf * 8 + g];
                bf[nf][0] = p[0];
                bf[nf][1] = p[4 * BS_PITCH];
            }
#pragma unroll
            for (int mf = 0; mf < 2; ++mf)
#pragma unroll
                for (int nf = 0; nf < 8; ++nf)
                    mma_tf32(acc[mf][nf], af[mf], bf[nf]);
        }
        if (it + 1 < NIT) ST_TILE(buf ^ 1);
        __syncthreads();
    }

#pragma unroll
    for (int mf = 0; mf < 2; ++mf) {
        int r0 = m0 + wm * 32 + mf * 16 + g;
#pragma unroll
        for (int nf = 0; nf < 8; ++nf) {
            int c = n0 + wn * 64 + nf * 8 + 2 * tg;
            float b0 = 0.f, b1 = 0.f;
            if (BIAS) { b0 = bias[c]; b1 = bias[c + 1]; }
            if (TRANS) {
                // C^T layout: Ct[c][r]
                C[(size_t)c * T_LEN + r0]           = acc[mf][nf][0] + b0;
                C[(size_t)(c + 1) * T_LEN + r0]     = acc[mf][nf][1] + b1;
                C[(size_t)c * T_LEN + r0 + 8]       = acc[mf][nf][2] + b0;
                C[(size_t)(c + 1) * T_LEN + r0 + 8] = acc[mf][nf][3] + b1;
            } else {
                float2 v0 = { acc[mf][nf][0] + b0, acc[mf][nf][1] + b1 };
                float2 v1 = { acc[mf][nf][2] + b0, acc[mf][nf][3] + b1 };
                *(float2*)&C[(size_t)r0 * N + c]       = v0;
                *(float2*)&C[(size_t)(r0 + 8) * N + c] = v1;
            }
        }
    }
#undef LD_TILE
#undef ST_TILE
}

__global__ __launch_bounds__(256)
void gemm_tc_bias(const float* __restrict__ A,
                  const float* __restrict__ W0, const float* __restrict__ W1,
                  const float* __restrict__ bias0, const float* __restrict__ bias1,
                  float* __restrict__ C0, float* __restrict__ C1,
                  int N, int K)
{
    if (blockIdx.z == 0)
        gemm_body<true, false>(A, W0, bias0, C0, K, N, blockIdx.y * 128, blockIdx.x * 128, 0, K);
    else
        gemm_body<true, true >(A, W1, bias1, C1, K, N, blockIdx.y * 128, blockIdx.x * 128, 0, K);
}

__global__ __launch_bounds__(256)
void gemm_tc_bias_plain(const float* __restrict__ A, const float* __restrict__ W,
                        const float* __restrict__ bias, float* __restrict__ C,
                        int N, int K)
{
    gemm_body<true, false>(A, W, bias, C, K, N, blockIdx.y * 128, blockIdx.x * 128, 0, K);
}

__global__ __launch_bounds__(256)
void gemm_tc_splitk(const float* __restrict__ A, const float* __restrict__ W,
                    float* __restrict__ Cpart, int N, int lda, int kPer)
{
    int z = blockIdx.z;
    gemm_body<false, false>(A, W, nullptr, Cpart + (size_t)z * T_LEN * DMODEL,
                            lda, N, blockIdx.y * 128, blockIdx.x * 128, z * kPer, kPer);
}

// ---------------------------------------------------------------------------
// RoPE (in place) + key_self/ATTN_SCALE folding into K rows.
// ---------------------------------------------------------------------------
__global__ __launch_bounds__(256)
void rope_kernel(float* __restrict__ Q, float* __restrict__ K)
{
    int gw   = blockIdx.x * 8 + (threadIdx.x >> 5);
    int lane = threadIdx.x & 31;
    int slot = gw % (HQ + HK);
    int t    = gw / (HQ + HK);

    bool isK = (slot >= HQ);
    float* ptr = isK ? (K + (size_t)t * DMODEL + (slot - HQ) * DH)
                     : (Q + (size_t)t * QDIM + slot * DH);

    float x1 = ptr[2 * lane];
    float x2 = ptr[2 * lane + 1];

    float inv = 1.0f / powf(10000.0f, (float)(2 * lane) / 64.0f);
    float fr  = (float)t * inv;
    float s, c;
    sincosf(fr, &s, &c);

    float o1 = x1 * c - x2 * s;
    float o2 = x1 * s + x2 * c;

    if (isK) {
        float nrm = x1 * x1 + x2 * x2;
#pragma unroll
        for (int off = 16; off; off >>= 1)
            nrm += __shfl_xor_sync(0xffffffffu, nrm, off);
        float ks  = fmaxf(nrm, 1e-6f);
        float scl = ATTN_SCALE * rsqrtf(ks);
        o1 *= scl;
        o2 *= scl;
    }
    __syncwarp();
    ptr[lane]      = o1;
    ptr[lane + 32] = o2;
}

// ===========================================================================
// Tensor-core attention v2.
//  - Q A-fragments held in registers for the whole kt loop (no Q LDS in loop)
//  - V pre-transposed in gmem -> Vt tile load is identical to K (no conflicts)
//  - separate K / Vt / Ws buffers; 3 syncs per kt tile
// ===========================================================================
#define APITCH 68
#define ATTN_SMEM_BYTES ((3 * 64 * APITCH + 128 + 64) * 4)

__global__ __launch_bounds__(256)
void attn_tc_kernel(const float* __restrict__ sinks, const float* __restrict__ v_nulls)
{
    extern __shared__ uint32_t smu[];
    uint32_t* Ks  = smu;                    // 64 x APITCH (K rows, tf32)
    uint32_t* Vts = Ks + 64 * APITCH;       // 64 x APITCH (V^T rows = dh)
    uint32_t* Ws  = Vts + 64 * APITCH;      // activated weights (also Q staging)
    float* RSm = (float*)(Ws + 64 * APITCH);
    float* Tot = RSm + 128;

    int head = blockIdx.y;
    int qt   = (gridDim.x - 1) - blockIdx.x;   // heavy tiles first
    int kvh  = head & (HK - 1);
    int tid  = threadIdx.x;
    int lane = tid & 31, wid = tid >> 5;
    int wm = wid & 3, wn = wid >> 2;
    int g = lane >> 2, tg = lane & 3;
    float sink = sinks[head];

    // ---- stage Q through Ws buffer, hoist A-fragments to registers
#pragma unroll
    for (int i = 0; i < 4; ++i) {
        int idx = tid + 256 * i;
        int r = idx >> 4, c = (idx & 15) * 4;
        float4 v = *(const float4*)&g_Q[(size_t)(qt * 64 + r) * QDIM + head * DH + c];
        uint32_t* p = &Ws[r * APITCH + c];
        p[0] = f2tf(v.x); p[1] = f2tf(v.y); p[2] = f2tf(v.z); p[3] = f2tf(v.w);
    }
    __syncthreads();
    uint32_t afq[8][4];
    {
        const uint32_t* p0 = &Ws[(wm * 16 + g) * APITCH + tg];
#pragma unroll
        for (int ks = 0; ks < 8; ++ks) {
            const uint32_t* p = p0 + ks * 8;
            afq[ks][0] = p[0];
            afq[ks][1] = p[8 * APITCH];
            afq[ks][2] = p[4];
            afq[ks][3] = p[8 * APITCH + 4];
        }
    }

    float oacc[4][4];
#pragma unroll
    for (int nf = 0; nf < 4; ++nf)
#pragma unroll
        for (int q = 0; q < 4; ++q) oacc[nf][q] = 0.f;
    float rs0 = 0.f, rs1 = 0.f;

    for (int kt = 0; kt <= qt; ++kt) {
        __syncthreads();   // prior WV reads (Ws, Vt) and S reads (K) complete
        // ---- load K tile + Vt tile (both straight copies, conflict-free)
#pragma unroll
        for (int i = 0; i < 4; ++i) {
            int idx = tid + 256 * i;
            int r = idx >> 4, c = (idx & 15) * 4;
            float4 v = *(const float4*)&g_K[(size_t)(kt * 64 + r) * DMODEL + kvh * DH + c];
            uint32_t* p = &Ks[r * APITCH + c];
            p[0] = f2tf(v.x); p[1] = f2tf(v.y); p[2] = f2tf(v.z); p[3] = f2tf(v.w);
        }
#pragma unroll
        for (int i = 0; i < 4; ++i) {
            int idx = tid + 256 * i;
            int d = idx >> 4, j = (idx & 15) * 4;
            float4 v = *(const float4*)&g_Vt[(size_t)(kvh * DH + d) * T_LEN + kt * 64 + j];
            uint32_t* p = &Vts[d * APITCH + j];
            p[0] = f2tf(v.x); p[1] = f2tf(v.y); p[2] = f2tf(v.z); p[3] = f2tf(v.w);
        }
        __syncthreads();

        // ---- scores: S = Q @ K^T  (A-frags from registers)
        float sacc[4][4];
#pragma unroll
        for (int nf = 0; nf < 4; ++nf)
#pragma unroll
            for (int q = 0; q < 4; ++q) sacc[nf][q] = 0.f;

#pragma unroll
        for (int ks = 0; ks < 8; ++ks) {
            uint32_t bf[4][2];
#pragma unroll
            for (int nf = 0; nf < 4; ++nf) {
                const uint32_t* bp = &Ks[(wn * 32 + nf * 8 + g) * APITCH + ks * 8 + tg];
                bf[nf][0] = bp[0]; bf[nf][1] = bp[4];
            }
#pragma unroll
            for (int nf = 0; nf < 4; ++nf)
                mma_tf32(sacc[nf], afq[ks], bf[nf]);
        }

        // ---- activation in registers -> Ws (tf32)
        bool diag = (kt == qt);
        int li0 = wm * 16 + g;
        int gi0 = qt * 64 + li0;
#pragma unroll
        for (int nf = 0; nf < 4; ++nf) {
            int ljc = wn * 32 + nf * 8 + 2 * tg;
            int gj  = kt * 64 + ljc;
            float w[4];
#pragma unroll
            for (int q = 0; q < 4; ++q) {
                float x = fminf(sacc[nf][q], 60.f);
                float t = f_ex2(x * 1.44269504f);
                float u = f_lg2(1.0f + t);
                float ww = 0.69314718f * u * f_rcp(1.0f + f_ex2(-SILU_SCALE * u));
                int gi = gi0 + ((q >> 1) << 3);
                int gjj = gj + (q & 1);
                if ((diag && gjj > gi) || ww < sink) ww = 0.f;
                w[q] = ww;
            }
            rs0 += w[0] + w[1];
            rs1 += w[2] + w[3];
            uint2 s0 = { f2tf(w[0]), f2tf(w[1]) };
            uint2 s1 = { f2tf(w[2]), f2tf(w[3]) };
            *(uint2*)&Ws[li0 * APITCH + ljc]       = s0;
            *(uint2*)&Ws[(li0 + 8) * APITCH + ljc] = s1;
        }
        __syncthreads();   // Ws visible to all warps

        // ---- O += W @ V   (A = Ws rows, B = Vt rows)
#pragma unroll
        for (int ks = 0; ks < 8; ++ks) {
            uint32_t af[4], bf[4][2];
            const uint32_t* ap = &Ws[(wm * 16 + g) * APITCH + ks * 8 + tg];
            af[0] = ap[0]; af[1] = ap[8 * APITCH];
            af[2] = ap[4]; af[3] = ap[8 * APITCH + 4];
#pragma unroll
            for (int nf = 0; nf < 4; ++nf) {
                const uint32_t* bp = &Vts[(wn * 32 + nf * 8 + g) * APITCH + ks * 8 + tg];
                bf[nf][0] = bp[0]; bf[nf][1] = bp[4];
            }
#pragma unroll
            for (int nf = 0; nf < 4; ++nf)
                mma_tf32(oacc[nf], af, bf[nf]);
        }
    }

    // ---- row-sum reduction
    __syncthreads();
    rs0 += __shfl_xor_sync(0xffffffffu, rs0, 1);
    rs0 += __shfl_xor_sync(0xffffffffu, rs0, 2);
    rs1 += __shfl_xor_sync(0xffffffffu, rs1, 1);
    rs1 += __shfl_xor_sync(0xffffffffu, rs1, 2);
    if (tg == 0) {
        RSm[wid * 16 + g]     = rs0;
        RSm[wid * 16 + 8 + g] = rs1;
    }
    __syncthreads();
    if (tid < 64)
        Tot[tid] = RSm[(tid >> 4) * 16 + (tid & 15)]
                 + RSm[((tid >> 4) + 4) * 16 + (tid & 15)] + sink + 1e-6f;
    __syncthreads();

    // ---- epilogue
    int li0 = wm * 16 + g;
    float invT0 = 1.0f / Tot[li0];
    float invT1 = 1.0f / Tot[li0 + 8];
#pragma unroll
    for (int nf = 0; nf < 4; ++nf) {
        int dloc = wn * 32 + nf * 8 + 2 * tg;
        float vn0 = v_nulls[head * DH + dloc];
        float vn1 = v_nulls[head * DH + dloc + 1];
        float2 o0 = { (oacc[nf][0] + sink * vn0) * invT0,
                      (oacc[nf][1] + sink * vn1) * invT0 };
        float2 o1 = { (oacc[nf][2] + sink * vn0) * invT1,
                      (oacc[nf][3] + sink * vn1) * invT1 };
        *(float2*)&g_OUT[(size_t)(qt * 64 + li0) * QDIM + head * DH + dloc]     = o0;
        *(float2*)&g_OUT[(size_t)(qt * 64 + li0 + 8) * QDIM + head * DH + dloc] = o1;
    }
}

// ---------------------------------------------------------------------------
// Final reduce: Y = 0.25 * (sum of 4 K-split partials + sum_br bias)
// ---------------------------------------------------------------------------
__global__ __launch_bounds__(256)
void reduce_out_kernel(const float* __restrict__ part, const float* __restrict__ wob,
                       float* __restrict__ out)
{
    int idx = blockIdx.x * 256 + threadIdx.x;
    int d = idx & (DMODEL - 1);
    float s = part[idx] + part[idx + 1048576] + part[idx + 2097152] + part[idx + 3145728];
    float b = wob[d] + wob[DMODEL + d] + wob[2 * DMODEL + d] + wob[3 * DMODEL + d];
    out[idx] = 0.25f * (s + b);
}

// ---------------------------------------------------------------------------
extern "C" void kernel_launch(void* const* d_in, const int* in_sizes, int n_in,
                              void* d_out, int out_size)
{
    const float* X        = (const float*)d_in[0];
    const float* W_Q      = (const float*)d_in[1];
    const float* b_Q      = (const float*)d_in[2];
    const float* W_K      = (const float*)d_in[3];
    const float* b_K      = (const float*)d_in[4];
    const float* W_V      = (const float*)d_in[5];
    const float* b_V      = (const float*)d_in[6];
    const float* sinks    = (const float*)d_in[7];
    const float* v_nulls  = (const float*)d_in[8];
    const float* W_O      = (const float*)d_in[9];
    const float* W_O_bias = (const float*)d_in[10];
    float* out = (float*)d_out;

    float *Qp, *Kp, *Vtp, *OUTp, *PARTp;
    cudaGetSymbolAddress((void**)&Qp,    g_Q);
    cudaGetSymbolAddress((void**)&Kp,    g_K);
    cudaGetSymbolAddress((void**)&Vtp,   g_Vt);
    cudaGetSymbolAddress((void**)&OUTp,  g_OUT);
    cudaGetSymbolAddress((void**)&PARTp, g_part);

    cudaFuncSetAttribute(gemm_tc_bias, cudaFuncAttributeMaxDynamicSharedMemorySize, GEMM_SMEM_BYTES);
    cudaFuncSetAttribute(gemm_tc_bias_plain, cudaFuncAttributeMaxDynamicSharedMemorySize, GEMM_SMEM_BYTES);
    cudaFuncSetAttribute(gemm_tc_splitk, cudaFuncAttributeMaxDynamicSharedMemorySize, GEMM_SMEM_BYTES);
    cudaFuncSetAttribute(attn_tc_kernel, cudaFuncAttributeMaxDynamicSharedMemorySize, ATTN_SMEM_BYTES);

    // Q projection
    gemm_tc_bias_plain<<<dim3(QDIM / 128, T_LEN / 128, 1), 256, GEMM_SMEM_BYTES>>>(
        X, W_Q, b_Q, Qp, QDIM, DMODEL);
    // K (normal) and V (transposed output) projections
    gemm_tc_bias<<<dim3(DMODEL / 128, T_LEN / 128, 2), 256, GEMM_SMEM_BYTES>>>(
        X, W_K, W_V, b_K, b_V, Kp, Vtp, DMODEL, DMODEL);
    // RoPE + key_self folding
    rope_kernel<<<10240, 256>>>(Qp, Kp);
    // tensor-core attention
    attn_tc_kernel<<<dim3(16, 64), 256, ATTN_SMEM_BYTES>>>(sinks, v_nulls);
    // output projection, split-K=4
    gemm_tc_splitk<<<dim3(DMODEL / 128, T_LEN / 128, 4), 256, GEMM_SMEM_BYTES>>>(
        OUTp, W_O, PARTp, DMODEL, QDIM, 1024);
    reduce_out_kernel<<<4096, 256>>>(PARTp, W_O_bias, out);
}

// round 6
// speedup vs baseline: 2.5355x; 1.0148x over previous
#include <cuda_runtime.h>
#include <math.h>
#include <stdint.h>

#define T_LEN   1024
#define DMODEL  1024
#define QDIM    4096
#define HQ      64
#define HK      16
#define DH      64
#define SILU_SCALE 1.8137993642342178f   /* pi / sqrt(3) */
#define ATTN_SCALE 0.125f                /* DH^-0.5 */

static __device__ float g_Q[T_LEN * QDIM];
static __device__ float g_K[T_LEN * DMODEL];
static __device__ float g_Vt[DMODEL * T_LEN];   // V transposed: [d][t]
static __device__ float g_OUT[T_LEN * QDIM];
static __device__ float g_part[8 * T_LEN * DMODEL];

// ===========================================================================
// fast-math + mma + cp.async helpers
// ===========================================================================
__device__ __forceinline__ float f_ex2(float x) { float y; asm("ex2.approx.ftz.f32 %0,%1;" : "=f"(y) : "f"(x)); return y; }
__device__ __forceinline__ float f_lg2(float x) { float y; asm("lg2.approx.ftz.f32 %0,%1;" : "=f"(y) : "f"(x)); return y; }
__device__ __forceinline__ float f_rcp(float x) { float y; asm("rcp.approx.ftz.f32 %0,%1;" : "=f"(y) : "f"(x)); return y; }
__device__ __forceinline__ uint32_t f2tf(float x) { uint32_t r; asm("cvt.rna.tf32.f32 %0,%1;" : "=r"(r) : "f"(x)); return r; }
__device__ __forceinline__ uint32_t smem_u32(const void* p) {
    uint32_t a;
    asm("{ .reg .u64 t; cvta.to.shared.u64 t, %1; cvt.u32.u64 %0, t; }" : "=r"(a) : "l"(p));
    return a;
}
__device__ __forceinline__ void cp_async16(uint32_t dst, const void* src) {
    asm volatile("cp.async.cg.shared.global [%0], [%1], 16;" :: "r"(dst), "l"(src));
}
#define CP_COMMIT() asm volatile("cp.async.commit_group;" ::: "memory")
#define CP_WAIT0()  asm volatile("cp.async.wait_group 0;"  ::: "memory")

__device__ __forceinline__ void mma_tf32(float* d, const uint32_t* a, const uint32_t* b) {
    asm volatile(
        "mma.sync.aligned.m16n8k8.row.col.f32.tf32.tf32.f32 "
        "{%0,%1,%2,%3}, {%4,%5,%6,%7}, {%8,%9}, {%0,%1,%2,%3};"
        : "+f"(d[0]), "+f"(d[1]), "+f"(d[2]), "+f"(d[3])
        : "r"(a[0]), "r"(a[1]), "r"(a[2]), "r"(a[3]), "r"(b[0]), "r"(b[1]));
}

// ===========================================================================
// Dense tf32 GEMM: 128x128 tile, BK=32, 8 warps (4m x 2n).
// TRANS: output written transposed + tf32-rounded (for V^T).
// ===========================================================================
#define AS_PITCH 36
#define BS_PITCH 136
#define AS_WORDS (128 * AS_PITCH)
#define BS_WORDS (32 * BS_PITCH)
#define GEMM_SMEM_BYTES ((2 * AS_WORDS + 2 * BS_WORDS) * 4)

template <bool BIAS, bool TRANS>
__device__ __forceinline__ void gemm_body(
    const float* __restrict__ A, const float* __restrict__ W,
    const float* __restrict__ bias, float* __restrict__ C,
    int lda, int N, int m0, int n0, int kbase, int kLen)
{
    extern __shared__ uint32_t sm[];
    uint32_t* AsBuf[2] = { sm, sm + AS_WORDS };
    uint32_t* BsBuf[2] = { sm + 2 * AS_WORDS, sm + 2 * AS_WORDS + BS_WORDS };

    int tid  = threadIdx.x;
    int lane = tid & 31, wid = tid >> 5;
    int wm = wid & 3, wn = wid >> 2;
    int g = lane >> 2, tg = lane & 3;

    float acc[2][8][4];
#pragma unroll
    for (int mf = 0; mf < 2; ++mf)
#pragma unroll
        for (int nf = 0; nf < 8; ++nf)
#pragma unroll
            for (int q = 0; q < 4; ++q) acc[mf][nf][q] = 0.f;

    float4 pa[4], pb[4];
    int arow = tid >> 3, aqc = tid & 7;
    int brow = tid >> 5, bnq = tid & 31;

#define LD_TILE(k0)                                                             \
    do {                                                                        \
        _Pragma("unroll")                                                       \
        for (int i = 0; i < 4; ++i)                                             \
            pa[i] = *(const float4*)&A[(size_t)(m0 + arow + 32 * i) * lda + (k0) + 4 * aqc]; \
        _Pragma("unroll")                                                       \
        for (int i = 0; i < 4; ++i)                                             \
            pb[i] = *(const float4*)&W[(size_t)((k0) + brow + 8 * i) * N + n0 + 4 * bnq];    \
    } while (0)

#define ST_TILE(buf)                                                            \
    do {                                                                        \
        _Pragma("unroll")                                                       \
        for (int i = 0; i < 4; ++i) {                                           \
            uint32_t* p = &AsBuf[buf][(arow + 32 * i) * AS_PITCH + 4 * aqc];    \
            p[0] = f2tf(pa[i].x); p[1] = f2tf(pa[i].y);                         \
            p[2] = f2tf(pa[i].z); p[3] = f2tf(pa[i].w);                         \
        }                                                                       \
        _Pragma("unroll")                                                       \
        for (int i = 0; i < 4; ++i) {                                           \
            uint32_t* p = &BsBuf[buf][(brow + 8 * i) * BS_PITCH + 4 * bnq];     \
            p[0] = f2tf(pb[i].x); p[1] = f2tf(pb[i].y);                         \
            p[2] = f2tf(pb[i].z); p[3] = f2tf(pb[i].w);                         \
        }                                                                       \
    } while (0)

    LD_TILE(kbase);
    ST_TILE(0);
    __syncthreads();

    int NIT = kLen / 32;
    for (int it = 0; it < NIT; ++it) {
        int buf = it & 1;
        if (it + 1 < NIT) LD_TILE(kbase + (it + 1) * 32);

        const uint32_t* As = AsBuf[buf];
        const uint32_t* Bs = BsBuf[buf];
#pragma unroll
        for (int ks = 0; ks < 4; ++ks) {
            uint32_t af[2][4], bf[8][2];
#pragma unroll
            for (int mf = 0; mf < 2; ++mf) {
                const uint32_t* p = &As[(wm * 32 + mf * 16 + g) * AS_PITCH + ks * 8 + tg];
                af[mf][0] = p[0];
                af[mf][1] = p[8 * AS_PITCH];
                af[mf][2] = p[4];
                af[mf][3] = p[8 * AS_PITCH + 4];
            }
#pragma unroll
            for (int nf = 0; nf < 8; ++nf) {
                const uint32_t* p = &Bs[(ks * 8 + tg) * BS_PITCH + wn * 64 + nf * 8 + g];
                bf[nf][0] = p[0];
                bf[nf][1] = p[4 * BS_PITCH];
            }
#pragma unroll
            for (int mf = 0; mf < 2; ++mf)
#pragma unroll
                for (int nf = 0; nf < 8; ++nf)
                    mma_tf32(acc[mf][nf], af[mf], bf[nf]);
        }
        if (it + 1 < NIT) ST_TILE(buf ^ 1);
        __syncthreads();
    }

#pragma unroll
    for (int mf = 0; mf < 2; ++mf) {
        int r0 = m0 + wm * 32 + mf * 16 + g;
#pragma unroll
        for (int nf = 0; nf < 8; ++nf) {
            int c = n0 + wn * 64 + nf * 8 + 2 * tg;
            float b0 = 0.f, b1 = 0.f;
            if (BIAS) { b0 = bias[c]; b1 = bias[c + 1]; }
            if (TRANS) {
                // V^T layout, tf32-rounded so attention can cp.async raw bits
                C[(size_t)c * T_LEN + r0]           = __uint_as_float(f2tf(acc[mf][nf][0] + b0));
                C[(size_t)(c + 1) * T_LEN + r0]     = __uint_as_float(f2tf(acc[mf][nf][1] + b1));
                C[(size_t)c * T_LEN + r0 + 8]       = __uint_as_float(f2tf(acc[mf][nf][2] + b0));
                C[(size_t)(c + 1) * T_LEN + r0 + 8] = __uint_as_float(f2tf(acc[mf][nf][3] + b1));
            } else {
                float2 v0 = { acc[mf][nf][0] + b0, acc[mf][nf][1] + b1 };
                float2 v1 = { acc[mf][nf][2] + b0, acc[mf][nf][3] + b1 };
                *(float2*)&C[(size_t)r0 * N + c]       = v0;
                *(float2*)&C[(size_t)(r0 + 8) * N + c] = v1;
            }
        }
    }
#undef LD_TILE
#undef ST_TILE
}

// Fused Q/K/V projections: 48 x-tiles (32 Q, 8 K, 8 V-transposed)
__global__ __launch_bounds__(256)
void gemm_qkv(const float* __restrict__ X,
              const float* __restrict__ W_Q, const float* __restrict__ b_Q,
              const float* __restrict__ W_K, const float* __restrict__ b_K,
              const float* __restrict__ W_V, const float* __restrict__ b_V,
              float* __restrict__ Qo, float* __restrict__ Ko, float* __restrict__ Vto)
{
    int bx = blockIdx.x, m0 = blockIdx.y * 128;
    if (bx < 32)
        gemm_body<true, false>(X, W_Q, b_Q, Qo, DMODEL, QDIM, m0, bx * 128, 0, DMODEL);
    else if (bx < 40)
        gemm_body<true, false>(X, W_K, b_K, Ko, DMODEL, DMODEL, m0, (bx - 32) * 128, 0, DMODEL);
    else
        gemm_body<true, true >(X, W_V, b_V, Vto, DMODEL, DMODEL, m0, (bx - 40) * 128, 0, DMODEL);
}

__global__ __launch_bounds__(256)
void gemm_tc_splitk(const float* __restrict__ A, const float* __restrict__ W,
                    float* __restrict__ Cpart, int N, int lda, int kPer)
{
    int z = blockIdx.z;
    gemm_body<false, false>(A, W, nullptr, Cpart + (size_t)z * T_LEN * DMODEL,
                            lda, N, blockIdx.y * 128, blockIdx.x * 128, z * kPer, kPer);
}

// ---------------------------------------------------------------------------
// RoPE (in place) + key_self/ATTN_SCALE folding; writes tf32-rounded Q and K
// so the attention kernel can cp.async raw bits losslessly.
// ---------------------------------------------------------------------------
__global__ __launch_bounds__(256)
void rope_kernel(float* __restrict__ Q, float* __restrict__ K)
{
    int gw   = blockIdx.x * 8 + (threadIdx.x >> 5);
    int lane = threadIdx.x & 31;
    int slot = gw % (HQ + HK);
    int t    = gw / (HQ + HK);

    bool isK = (slot >= HQ);
    float* ptr = isK ? (K + (size_t)t * DMODEL + (slot - HQ) * DH)
                     : (Q + (size_t)t * QDIM + slot * DH);

    float x1 = ptr[2 * lane];
    float x2 = ptr[2 * lane + 1];

    float inv = 1.0f / powf(10000.0f, (float)(2 * lane) / 64.0f);
    float fr  = (float)t * inv;
    float s, c;
    sincosf(fr, &s, &c);

    float o1 = x1 * c - x2 * s;
    float o2 = x1 * s + x2 * c;

    if (isK) {
        float nrm = x1 * x1 + x2 * x2;
#pragma unroll
        for (int off = 16; off; off >>= 1)
            nrm += __shfl_xor_sync(0xffffffffu, nrm, off);
        float ks  = fmaxf(nrm, 1e-6f);
        float scl = ATTN_SCALE * rsqrtf(ks);
        o1 *= scl;
        o2 *= scl;
    }
    __syncwarp();
    ptr[lane]      = __uint_as_float(f2tf(o1));
    ptr[lane + 32] = __uint_as_float(f2tf(o2));
}

// ===========================================================================
// Tensor-core attention v3: cp.async double-buffered K/Vt tiles (loads for
// kt+1 overlap S-mma/activation of kt), single Ws buffer, 2 syncs/iter,
// Q A-fragments in registers. Inputs pre-rounded to tf32 -> raw async copies.
// ===========================================================================
#define APITCH 68
#define TILE_WORDS (64 * APITCH)
// SMEM: Ks[2], Vts[2], Ws, RSm[128], Tot[64]
#define ATTN_SMEM_WORDS (5 * TILE_WORDS + 128 + 64)
#define ATTN_SMEM_BYTES (ATTN_SMEM_WORDS * 4)

__global__ __launch_bounds__(256)
void attn_tc_kernel(const float* __restrict__ sinks, const float* __restrict__ v_nulls)
{
    extern __shared__ uint32_t smu[];
    uint32_t* KsB[2]  = { smu,                  smu + TILE_WORDS };
    uint32_t* VtsB[2] = { smu + 2 * TILE_WORDS, smu + 3 * TILE_WORDS };
    uint32_t* Ws      = smu + 4 * TILE_WORDS;
    float* RSm = (float*)(smu + 5 * TILE_WORDS);
    float* Tot = RSm + 128;

    int head = blockIdx.y;
    int qt   = (gridDim.x - 1) - blockIdx.x;   // heavy tiles first
    int kvh  = head & (HK - 1);
    int tid  = threadIdx.x;
    int lane = tid & 31, wid = tid >> 5;
    int wm = wid & 3, wn = wid >> 2;
    int g = lane >> 2, tg = lane & 3;
    float sink = sinks[head];

    // per-thread copy slots: idx = tid + 256*i -> (row, col4)
    int crow = tid >> 4, ccol = (tid & 15) * 4;
    uint32_t ksAddr[2], vtAddr[2];
#pragma unroll
    for (int b = 0; b < 2; ++b) {
        ksAddr[b] = smem_u32(&KsB[b][crow * APITCH + ccol]);
        vtAddr[b] = smem_u32(&VtsB[b][crow * APITCH + ccol]);
    }
    const float* kSrc  = &g_K[(size_t)crow * DMODEL + kvh * DH + ccol];
    const float* vtSrc = &g_Vt[(size_t)(kvh * DH + crow) * T_LEN + ccol];

#define ISSUE_TILES(kt_, b_)                                                     \
    do {                                                                         \
        _Pragma("unroll")                                                        \
        for (int i = 0; i < 4; ++i)                                              \
            cp_async16(ksAddr[b_] + i * 16 * APITCH * 4,                         \
                       kSrc + (size_t)((kt_) * 64 + i * 16) * DMODEL);           \
        _Pragma("unroll")                                                        \
        for (int i = 0; i < 4; ++i)                                              \
            cp_async16(vtAddr[b_] + i * 16 * APITCH * 4,                         \
                       vtSrc + (size_t)(i * 16) * T_LEN + (kt_) * 64);           \
        CP_COMMIT();                                                             \
    } while (0)

    // prologue: start kt=0 loads, stage Q through Ws, hoist Q fragments
    ISSUE_TILES(0, 0);
#pragma unroll
    for (int i = 0; i < 4; ++i) {
        int idx = tid + 256 * i;
        int r = idx >> 4, c = (idx & 15) * 4;
        float4 v = *(const float4*)&g_Q[(size_t)(qt * 64 + r) * QDIM + head * DH + c];
        uint32_t* p = &Ws[r * APITCH + c];
        p[0] = __float_as_uint(v.x); p[1] = __float_as_uint(v.y);
        p[2] = __float_as_uint(v.z); p[3] = __float_as_uint(v.w);
    }
    __syncthreads();
    uint32_t afq[8][4];
    {
        const uint32_t* p0 = &Ws[(wm * 16 + g) * APITCH + tg];
#pragma unroll
        for (int ks = 0; ks < 8; ++ks) {
            const uint32_t* p = p0 + ks * 8;
            afq[ks][0] = p[0];
            afq[ks][1] = p[8 * APITCH];
            afq[ks][2] = p[4];
            afq[ks][3] = p[8 * APITCH + 4];
        }
    }

    float oacc[4][4];
#pragma unroll
    for (int nf = 0; nf < 4; ++nf)
#pragma unroll
        for (int q = 0; q < 4; ++q) oacc[nf][q] = 0.f;
    float rs0 = 0.f, rs1 = 0.f;

    int li0 = wm * 16 + g;
    int gi0 = qt * 64 + li0;

    for (int kt = 0; kt <= qt; ++kt) {
        int b = kt & 1;
        CP_WAIT0();
        __syncthreads();   // K[b]/Vt[b] visible; WV(kt-1) done -> Ws reusable

        const uint32_t* Ks  = KsB[b];
        const uint32_t* Vts = VtsB[b];

        // ---- scores: S = Q @ K^T (A-frags in registers)
        float sacc[4][4];
#pragma unroll
        for (int nf = 0; nf < 4; ++nf)
#pragma unroll
            for (int q = 0; q < 4; ++q) sacc[nf][q] = 0.f;

#pragma unroll
        for (int ks = 0; ks < 8; ++ks) {
            uint32_t bf[4][2];
#pragma unroll
            for (int nf = 0; nf < 4; ++nf) {
                const uint32_t* bp = &Ks[(wn * 32 + nf * 8 + g) * APITCH + ks * 8 + tg];
                bf[nf][0] = bp[0]; bf[nf][1] = bp[4];
            }
#pragma unroll
            for (int nf = 0; nf < 4; ++nf)
                mma_tf32(sacc[nf], afq[ks], bf[nf]);
        }

        // ---- activation in registers -> Ws (tf32)
        bool diag = (kt == qt);
#pragma unroll
        for (int nf = 0; nf < 4; ++nf) {
            int ljc = wn * 32 + nf * 8 + 2 * tg;
            int gj  = kt * 64 + ljc;
            float w[4];
#pragma unroll
            for (int q = 0; q < 4; ++q) {
                float x = fminf(sacc[nf][q], 60.f);
                float t = f_ex2(x * 1.44269504f);
                float u = f_lg2(1.0f + t);
                float ww = 0.69314718f * u * f_rcp(1.0f + f_ex2(-SILU_SCALE * u));
                int gi = gi0 + ((q >> 1) << 3);
                int gjj = gj + (q & 1);
                if ((diag && gjj > gi) || ww < sink) ww = 0.f;
                w[q] = ww;
            }
            rs0 += w[0] + w[1];
            rs1 += w[2] + w[3];
            uint2 s0 = { f2tf(w[0]), f2tf(w[1]) };
            uint2 s1 = { f2tf(w[2]), f2tf(w[3]) };
            *(uint2*)&Ws[li0 * APITCH + ljc]       = s0;
            *(uint2*)&Ws[(li0 + 8) * APITCH + ljc] = s1;
        }
        __syncthreads();   // Ws visible; safe to overwrite K/Vt[b^1]

        // ---- prefetch next tile pair
        if (kt < qt) ISSUE_TILES(kt + 1, b ^ 1);

        // ---- O += W @ V
#pragma unroll
        for (int ks = 0; ks < 8; ++ks) {
            uint32_t af[4], bf[4][2];
            const uint32_t* ap = &Ws[li0 * APITCH + ks * 8 + tg];
            af[0] = ap[0]; af[1] = ap[8 * APITCH];
            af[2] = ap[4]; af[3] = ap[8 * APITCH + 4];
#pragma unroll
            for (int nf = 0; nf < 4; ++nf) {
                const uint32_t* bp = &Vts[(wn * 32 + nf * 8 + g) * APITCH + ks * 8 + tg];
                bf[nf][0] = bp[0]; bf[nf][1] = bp[4];
            }
#pragma unroll
            for (int nf = 0; nf < 4; ++nf)
                mma_tf32(oacc[nf], af, bf[nf]);
        }
    }
#undef ISSUE_TILES

    // ---- row-sum reduction
    __syncthreads();
    rs0 += __shfl_xor_sync(0xffffffffu, rs0, 1);
    rs0 += __shfl_xor_sync(0xffffffffu, rs0, 2);
    rs1 += __shfl_xor_sync(0xffffffffu, rs1, 1);
    rs1 += __shfl_xor_sync(0xffffffffu, rs1, 2);
    if (tg == 0) {
        RSm[wid * 16 + g]     = rs0;
        RSm[wid * 16 + 8 + g] = rs1;
    }
    __syncthreads();
    if (tid < 64)
        Tot[tid] = RSm[(tid >> 4) * 16 + (tid & 15)]
                 + RSm[((tid >> 4) + 4) * 16 + (tid & 15)] + sink + 1e-6f;
    __syncthreads();

    // ---- epilogue
    float invT0 = 1.0f / Tot[li0];
    float invT1 = 1.0f / Tot[li0 + 8];
#pragma unroll
    for (int nf = 0; nf < 4; ++nf) {
        int dloc = wn * 32 + nf * 8 + 2 * tg;
        float vn0 = v_nulls[head * DH + dloc];
        float vn1 = v_nulls[head * DH + dloc + 1];
        float2 o0 = { (oacc[nf][0] + sink * vn0) * invT0,
                      (oacc[nf][1] + sink * vn1) * invT0 };
        float2 o1 = { (oacc[nf][2] + sink * vn0) * invT1,
                      (oacc[nf][3] + sink * vn1) * invT1 };
        *(float2*)&g_OUT[(size_t)(qt * 64 + li0) * QDIM + head * DH + dloc]     = o0;
        *(float2*)&g_OUT[(size_t)(qt * 64 + li0 + 8) * QDIM + head * DH + dloc] = o1;
    }
}

// ---------------------------------------------------------------------------
// Final reduce: Y = 0.25 * (sum of 8 K-split partials + sum_br bias)
// ---------------------------------------------------------------------------
__global__ __launch_bounds__(256)
void reduce_out_kernel(const float* __restrict__ part, const float* __restrict__ wob,
                       float* __restrict__ out)
{
    int idx = blockIdx.x * 256 + threadIdx.x;
    int d = idx & (DMODEL - 1);
    float s = 0.f;
#pragma unroll
    for (int j = 0; j < 8; ++j) s += part[idx + j * (T_LEN * DMODEL)];
    float b = wob[d] + wob[DMODEL + d] + wob[2 * DMODEL + d] + wob[3 * DMODEL + d];
    out[idx] = 0.25f * (s + b);
}

// ---------------------------------------------------------------------------
extern "C" void kernel_launch(void* const* d_in, const int* in_sizes, int n_in,
                              void* d_out, int out_size)
{
    const float* X        = (const float*)d_in[0];
    const float* W_Q      = (const float*)d_in[1];
    const float* b_Q      = (const float*)d_in[2];
    const float* W_K      = (const float*)d_in[3];
    const float* b_K      = (const float*)d_in[4];
    const float* W_V      = (const float*)d_in[5];
    const float* b_V      = (const float*)d_in[6];
    const float* sinks    = (const float*)d_in[7];
    const float* v_nulls  = (const float*)d_in[8];
    const float* W_O      = (const float*)d_in[9];
    const float* W_O_bias = (const float*)d_in[10];
    float* out = (float*)d_out;

    float *Qp, *Kp, *Vtp, *OUTp, *PARTp;
    cudaGetSymbolAddress((void**)&Qp,    g_Q);
    cudaGetSymbolAddress((void**)&Kp,    g_K);
    cudaGetSymbolAddress((void**)&Vtp,   g_Vt);
    cudaGetSymbolAddress((void**)&OUTp,  g_OUT);
    cudaGetSymbolAddress((void**)&PARTp, g_part);

    cudaFuncSetAttribute(gemm_qkv, cudaFuncAttributeMaxDynamicSharedMemorySize, GEMM_SMEM_BYTES);
    cudaFuncSetAttribute(gemm_tc_splitk, cudaFuncAttributeMaxDynamicSharedMemorySize, GEMM_SMEM_BYTES);
    cudaFuncSetAttribute(attn_tc_kernel, cudaFuncAttributeMaxDynamicSharedMemorySize, ATTN_SMEM_BYTES);

    // fused Q/K/V projections (V written transposed + tf32-rounded)
    gemm_qkv<<<dim3(48, 8, 1), 256, GEMM_SMEM_BYTES>>>(
        X, W_Q, b_Q, W_K, b_K, W_V, b_V, Qp, Kp, Vtp);
    // RoPE + key_self folding + tf32 rounding of Q and K
    rope_kernel<<<10240, 256>>>(Qp, Kp);
    // pipelined tensor-core attention
    attn_tc_kernel<<<dim3(16, 64), 256, ATTN_SMEM_BYTES>>>(sinks, v_nulls);
    // output projection, split-K=8
    gemm_tc_splitk<<<dim3(DMODEL / 128, T_LEN / 128, 8), 256, GEMM_SMEM_BYTES>>>(
        OUTp, W_O, PARTp, DMODEL, QDIM, 512);
    reduce_out_kernel<<<4096, 256>>>(PARTp, W_O_bias, out);
}

// round 8
// speedup vs baseline: 3.2878x; 1.2967x over previous
#include <cuda_runtime.h>
#include <math.h>
#include <stdint.h>

#define T_LEN   1024
#define DMODEL  1024
#define QDIM    4096
#define HQ      64
#define HK      16
#define DH      64
#define SILU_SCALE 1.8137993642342178f   /* pi / sqrt(3) */
#define ATTN_SCALE 0.125f                /* DH^-0.5 */

static __device__ float g_Q[T_LEN * QDIM];
static __device__ float g_K[T_LEN * DMODEL];
static __device__ float g_Vt[DMODEL * T_LEN];   // V transposed: [d][t]
static __device__ float g_OUT[T_LEN * QDIM];
static __device__ float g_part[4 * T_LEN * DMODEL];
// tf32-prerounded operands (cp.async copies raw bits)
static __device__ float g_Xr[T_LEN * DMODEL];
static __device__ float g_WQr[DMODEL * QDIM];
static __device__ float g_WKr[DMODEL * DMODEL];
static __device__ float g_WVr[DMODEL * DMODEL];
static __device__ float g_WOr[QDIM * DMODEL];

// ===========================================================================
// helpers
// ===========================================================================
__device__ __forceinline__ float f_ex2(float x) { float y; asm("ex2.approx.ftz.f32 %0,%1;" : "=f"(y) : "f"(x)); return y; }
__device__ __forceinline__ float f_lg2(float x) { float y; asm("lg2.approx.ftz.f32 %0,%1;" : "=f"(y) : "f"(x)); return y; }
__device__ __forceinline__ float f_rcp(float x) { float y; asm("rcp.approx.ftz.f32 %0,%1;" : "=f"(y) : "f"(x)); return y; }
__device__ __forceinline__ uint32_t f2tf(float x) { uint32_t r; asm("cvt.rna.tf32.f32 %0,%1;" : "=r"(r) : "f"(x)); return r; }
__device__ __forceinline__ uint32_t smem_u32(const void* p) {
    uint32_t a;
    asm("{ .reg .u64 t; cvta.to.shared.u64 t, %1; cvt.u32.u64 %0, t; }" : "=r"(a) : "l"(p));
    return a;
}
__device__ __forceinline__ void cp_async16(uint32_t dst, const void* src) {
    asm volatile("cp.async.cg.shared.global [%0], [%1], 16;" :: "r"(dst), "l"(src));
}
#define CP_COMMIT() asm volatile("cp.async.commit_group;" ::: "memory")
#define CP_WAIT0()  asm volatile("cp.async.wait_group 0;"  ::: "memory")
#define CP_WAIT1()  asm volatile("cp.async.wait_group 1;"  ::: "memory")

__device__ __forceinline__ void mma_tf32(float* d, const uint32_t* a, const uint32_t* b) {
    asm volatile(
        "mma.sync.aligned.m16n8k8.row.col.f32.tf32.tf32.f32 "
        "{%0,%1,%2,%3}, {%4,%5,%6,%7}, {%8,%9}, {%0,%1,%2,%3};"
        : "+f"(d[0]), "+f"(d[1]), "+f"(d[2]), "+f"(d[3])
        : "r"(a[0]), "r"(a[1]), "r"(a[2]), "r"(a[3]), "r"(b[0]), "r"(b[1]));
}

// ---------------------------------------------------------------------------
// tf32 pre-rounding of GEMM operands (one pass; cp.async then copies raw bits)
// ---------------------------------------------------------------------------
__global__ __launch_bounds__(256)
void preround_all(const float* __restrict__ X, const float* __restrict__ WQ,
                  const float* __restrict__ WK, const float* __restrict__ WV,
                  const float* __restrict__ WO)
{
    int z = blockIdx.y;
    const float* s; float* d; int n4;
    switch (z) {
        case 0:  s = X;  d = g_Xr;  n4 = (T_LEN * DMODEL) / 4;  break;
        case 1:  s = WQ; d = g_WQr; n4 = (DMODEL * QDIM) / 4;   break;
        case 2:  s = WK; d = g_WKr; n4 = (DMODEL * DMODEL) / 4; break;
        case 3:  s = WV; d = g_WVr; n4 = (DMODEL * DMODEL) / 4; break;
        default: s = WO; d = g_WOr; n4 = (QDIM * DMODEL) / 4;   break;
    }
    int stride = gridDim.x * 256;
    for (int i = blockIdx.x * 256 + threadIdx.x; i < n4; i += stride) {
        float4 v = ((const float4*)s)[i];
        float4 o;
        o.x = __uint_as_float(f2tf(v.x));
        o.y = __uint_as_float(f2tf(v.y));
        o.z = __uint_as_float(f2tf(v.z));
        o.w = __uint_as_float(f2tf(v.w));
        ((float4*)d)[i] = o;
    }
}

// ===========================================================================
// cp.async 3-stage pipelined tf32 GEMM: 128x128 tile, BK=32, 8 warps (4m x 2n)
// Inputs MUST be tf32-prerounded. 2 CTAs/SM (regs<=128, smem ~105KB).
// ===========================================================================
#define AS_PITCH 36
#define BS_PITCH 136
#define AS_WORDS (128 * AS_PITCH)
#define BS_WORDS (32 * BS_PITCH)
#define NSTAGE 3
#define STG_WORDS (AS_WORDS + BS_WORDS)
#define GEMM_SMEM_BYTES (NSTAGE * STG_WORDS * 4)

template <bool BIAS, bool TRANS>
__device__ __forceinline__ void gemm_body(
    const float* __restrict__ A, const float* __restrict__ W,
    const float* __restrict__ bias, float* __restrict__ C,
    int lda, int N, int m0, int n0, int kbase, int kLen)
{
    extern __shared__ uint32_t sm[];
    int tid  = threadIdx.x;
    int lane = tid & 31, wid = tid >> 5;
    int wm = wid & 3, wn = wid >> 2;
    int g = lane >> 2, tg = lane & 3;

    int arow = tid >> 3, ac4 = (tid & 7) * 4;
    int brow = tid >> 5, bc4 = (tid & 31) * 4;

    const float* Abase = &A[(size_t)(m0 + arow) * lda + kbase + ac4];
    const float* Bbase = &W[(size_t)(kbase + brow) * N + n0 + bc4];

    uint32_t aDst[NSTAGE], bDst[NSTAGE];
#pragma unroll
    for (int s = 0; s < NSTAGE; ++s) {
        aDst[s] = smem_u32(&sm[s * STG_WORDS + arow * AS_PITCH + ac4]);
        bDst[s] = smem_u32(&sm[s * STG_WORDS + AS_WORDS + brow * BS_PITCH + bc4]);
    }

#define ISSUE(it_)                                                                \
    do {                                                                          \
        int s_ = (it_) % NSTAGE;                                                  \
        _Pragma("unroll")                                                         \
        for (int i = 0; i < 4; ++i)                                               \
            cp_async16(aDst[s_] + i * 32 * AS_PITCH * 4,                          \
                       Abase + (size_t)32 * i * lda + (it_) * 32);                \
        _Pragma("unroll")                                                         \
        for (int i = 0; i < 4; ++i)                                               \
            cp_async16(bDst[s_] + i * 8 * BS_PITCH * 4,                           \
                       Bbase + (size_t)((it_) * 32 + 8 * i) * N);                 \
        CP_COMMIT();                                                              \
    } while (0)

    float acc[2][8][4];
#pragma unroll
    for (int mf = 0; mf < 2; ++mf)
#pragma unroll
        for (int nf = 0; nf < 8; ++nf)
#pragma unroll
            for (int q = 0; q < 4; ++q) acc[mf][nf][q] = 0.f;

    int NIT = kLen / 32;
    ISSUE(0);
    if (NIT > 1) ISSUE(1);

    for (int it = 0; it < NIT; ++it) {
        int s = it % NSTAGE;
        CP_WAIT1();
        __syncthreads();
        if (it + 2 < NIT) ISSUE(it + 2);

        const uint32_t* As = sm + s * STG_WORDS;
        const uint32_t* Bs = As + AS_WORDS;
#pragma unroll
        for (int ks = 0; ks < 4; ++ks) {
            uint32_t af[2][4], bf[8][2];
#pragma unroll
            for (int mf = 0; mf < 2; ++mf) {
                const uint32_t* p = &As[(wm * 32 + mf * 16 + g) * AS_PITCH + ks * 8 + tg];
                af[mf][0] = p[0];
                af[mf][1] = p[8 * AS_PITCH];
                af[mf][2] = p[4];
                af[mf][3] = p[8 * AS_PITCH + 4];
            }
#pragma unroll
            for (int nf = 0; nf < 8; ++nf) {
                const uint32_t* p = &Bs[(ks * 8 + tg) * BS_PITCH + wn * 64 + nf * 8 + g];
                bf[nf][0] = p[0];
                bf[nf][1] = p[4 * BS_PITCH];
            }
#pragma unroll
            for (int mf = 0; mf < 2; ++mf)
#pragma unroll
                for (int nf = 0; nf < 8; ++nf)
                    mma_tf32(acc[mf][nf], af[mf], bf[nf]);
        }
        __syncthreads();
    }
#undef ISSUE

#pragma unroll
    for (int mf = 0; mf < 2; ++mf) {
        int r0 = m0 + wm * 32 + mf * 16 + g;
#pragma unroll
        for (int nf = 0; nf < 8; ++nf) {
            int c = n0 + wn * 64 + nf * 8 + 2 * tg;
            float b0 = 0.f, b1 = 0.f;
            if (BIAS) { b0 = bias[c]; b1 = bias[c + 1]; }
            if (TRANS) {
                // V^T layout, tf32-rounded so attention can cp.async raw bits
                C[(size_t)c * T_LEN + r0]           = __uint_as_float(f2tf(acc[mf][nf][0] + b0));
                C[(size_t)(c + 1) * T_LEN + r0]     = __uint_as_float(f2tf(acc[mf][nf][1] + b1));
                C[(size_t)c * T_LEN + r0 + 8]       = __uint_as_float(f2tf(acc[mf][nf][2] + b0));
                C[(size_t)(c + 1) * T_LEN + r0 + 8] = __uint_as_float(f2tf(acc[mf][nf][3] + b1));
            } else {
                float2 v0 = { acc[mf][nf][0] + b0, acc[mf][nf][1] + b1 };
                float2 v1 = { acc[mf][nf][2] + b0, acc[mf][nf][3] + b1 };
                *(float2*)&C[(size_t)r0 * N + c]       = v0;
                *(float2*)&C[(size_t)(r0 + 8) * N + c] = v1;
            }
        }
    }
}

// Fused Q/K/V projections: 48 x-tiles (32 Q, 8 K, 8 V-transposed)
__global__ __launch_bounds__(256, 2)
void gemm_qkv(const float* __restrict__ b_Q, const float* __restrict__ b_K,
              const float* __restrict__ b_V,
              float* __restrict__ Qo, float* __restrict__ Ko, float* __restrict__ Vto)
{
    int bx = blockIdx.x, m0 = blockIdx.y * 128;
    if (bx < 32)
        gemm_body<true, false>(g_Xr, g_WQr, b_Q, Qo, DMODEL, QDIM, m0, bx * 128, 0, DMODEL);
    else if (bx < 40)
        gemm_body<true, false>(g_Xr, g_WKr, b_K, Ko, DMODEL, DMODEL, m0, (bx - 32) * 128, 0, DMODEL);
    else
        gemm_body<true, true >(g_Xr, g_WVr, b_V, Vto, DMODEL, DMODEL, m0, (bx - 40) * 128, 0, DMODEL);
}

__global__ __launch_bounds__(256, 2)
void gemm_tc_splitk(float* __restrict__ Cpart, int kPer)
{
    int z = blockIdx.z;
    gemm_body<false, false>(g_OUT, g_WOr, nullptr, Cpart + (size_t)z * T_LEN * DMODEL,
                            QDIM, DMODEL, blockIdx.y * 128, blockIdx.x * 128, z * kPer, kPer);
}

// ---------------------------------------------------------------------------
// RoPE (in place) + key_self/ATTN_SCALE folding; writes tf32-rounded Q and K.
// ---------------------------------------------------------------------------
__global__ __launch_bounds__(256)
void rope_kernel(float* __restrict__ Q, float* __restrict__ K)
{
    int gw   = blockIdx.x * 8 + (threadIdx.x >> 5);
    int lane = threadIdx.x & 31;
    int slot = gw % (HQ + HK);
    int t    = gw / (HQ + HK);

    bool isK = (slot >= HQ);
    float* ptr = isK ? (K + (size_t)t * DMODEL + (slot - HQ) * DH)
                     : (Q + (size_t)t * QDIM + slot * DH);

    float x1 = ptr[2 * lane];
    float x2 = ptr[2 * lane + 1];

    float inv = 1.0f / powf(10000.0f, (float)(2 * lane) / 64.0f);
    float fr  = (float)t * inv;
    float s, c;
    sincosf(fr, &s, &c);

    float o1 = x1 * c - x2 * s;
    float o2 = x1 * s + x2 * c;

    if (isK) {
        float nrm = x1 * x1 + x2 * x2;
#pragma unroll
        for (int off = 16; off; off >>= 1)
            nrm += __shfl_xor_sync(0xffffffffu, nrm, off);
        float ks  = fmaxf(nrm, 1e-6f);
        float scl = ATTN_SCALE * rsqrtf(ks);
        o1 *= scl;
        o2 *= scl;
    }
    __syncwarp();
    ptr[lane]      = __uint_as_float(f2tf(o1));
    ptr[lane + 32] = __uint_as_float(f2tf(o2));
}

// ===========================================================================
// Tensor-core attention: cp.async double-buffered K/Vt tiles,
// Q A-frags in registers, activation in registers, OUT written tf32-rounded.
// ===========================================================================
#define APITCH 68
#define TILE_WORDS (64 * APITCH)
#define ATTN_SMEM_WORDS (5 * TILE_WORDS + 128 + 64)
#define ATTN_SMEM_BYTES (ATTN_SMEM_WORDS * 4)

__global__ __launch_bounds__(256)
void attn_tc_kernel(const float* __restrict__ sinks, const float* __restrict__ v_nulls)
{
    extern __shared__ uint32_t smu[];
    uint32_t* KsB[2]  = { smu,                  smu + TILE_WORDS };
    uint32_t* VtsB[2] = { smu + 2 * TILE_WORDS, smu + 3 * TILE_WORDS };
    uint32_t* Ws      = smu + 4 * TILE_WORDS;
    float* RSm = (float*)(smu + 5 * TILE_WORDS);
    float* Tot = RSm + 128;

    int head = blockIdx.y;
    int qt   = (gridDim.x - 1) - blockIdx.x;   // heavy tiles first
    int kvh  = head & (HK - 1);
    int tid  = threadIdx.x;
    int lane = tid & 31, wid = tid >> 5;
    int wm = wid & 3, wn = wid >> 2;
    int g = lane >> 2, tg = lane & 3;
    float sink = sinks[head];

    int crow = tid >> 4, ccol = (tid & 15) * 4;
    uint32_t ksAddr[2], vtAddr[2];
#pragma unroll
    for (int b = 0; b < 2; ++b) {
        ksAddr[b] = smem_u32(&KsB[b][crow * APITCH + ccol]);
        vtAddr[b] = smem_u32(&VtsB[b][crow * APITCH + ccol]);
    }
    const float* kSrc  = &g_K[(size_t)crow * DMODEL + kvh * DH + ccol];
    const float* vtSrc = &g_Vt[(size_t)(kvh * DH + crow) * T_LEN + ccol];

#define ISSUE_TILES(kt_, b_)                                                     \
    do {                                                                         \
        _Pragma("unroll")                                                        \
        for (int i = 0; i < 4; ++i)                                              \
            cp_async16(ksAddr[b_] + i * 16 * APITCH * 4,                         \
                       kSrc + (size_t)((kt_) * 64 + i * 16) * DMODEL);           \
        _Pragma("unroll")                                                        \
        for (int i = 0; i < 4; ++i)                                              \
            cp_async16(vtAddr[b_] + i * 16 * APITCH * 4,                         \
                       vtSrc + (size_t)(i * 16) * T_LEN + (kt_) * 64);           \
        CP_COMMIT();                                                             \
    } while (0)

    ISSUE_TILES(0, 0);
#pragma unroll
    for (int i = 0; i < 4; ++i) {
        int idx = tid + 256 * i;
        int r = idx >> 4, c = (idx & 15) * 4;
        float4 v = *(const float4*)&g_Q[(size_t)(qt * 64 + r) * QDIM + head * DH + c];
        uint32_t* p = &Ws[r * APITCH + c];
        p[0] = __float_as_uint(v.x); p[1] = __float_as_uint(v.y);
        p[2] = __float_as_uint(v.z); p[3] = __float_as_uint(v.w);
    }
    __syncthreads();
    uint32_t afq[8][4];
    {
        const uint32_t* p0 = &Ws[(wm * 16 + g) * APITCH + tg];
#pragma unroll
        for (int ks = 0; ks < 8; ++ks) {
            const uint32_t* p = p0 + ks * 8;
            afq[ks][0] = p[0];
            afq[ks][1] = p[8 * APITCH];
            afq[ks][2] = p[4];
            afq[ks][3] = p[8 * APITCH + 4];
        }
    }

    float oacc[4][4];
#pragma unroll
    for (int nf = 0; nf < 4; ++nf)
#pragma unroll
        for (int q = 0; q < 4; ++q) oacc[nf][q] = 0.f;
    float rs0 = 0.f, rs1 = 0.f;

    int li0 = wm * 16 + g;
    int gi0 = qt * 64 + li0;

    for (int kt = 0; kt <= qt; ++kt) {
        int b = kt & 1;
        CP_WAIT0();
        __syncthreads();

        const uint32_t* Ks  = KsB[b];
        const uint32_t* Vts = VtsB[b];

        float sacc[4][4];
#pragma unroll
        for (int nf = 0; nf < 4; ++nf)
#pragma unroll
            for (int q = 0; q < 4; ++q) sacc[nf][q] = 0.f;

#pragma unroll
        for (int ks = 0; ks < 8; ++ks) {
            uint32_t bf[4][2];
#pragma unroll
            for (int nf = 0; nf < 4; ++nf) {
                const uint32_t* bp = &Ks[(wn * 32 + nf * 8 + g) * APITCH + ks * 8 + tg];
                bf[nf][0] = bp[0]; bf[nf][1] = bp[4];
            }
#pragma unroll
            for (int nf = 0; nf < 4; ++nf)
                mma_tf32(sacc[nf], afq[ks], bf[nf]);
        }

        bool diag = (kt == qt);
#pragma unroll
        for (int nf = 0; nf < 4; ++nf) {
            int ljc = wn * 32 + nf * 8 + 2 * tg;
            int gj  = kt * 64 + ljc;
            float w[4];
#pragma unroll
            for (int q = 0; q < 4; ++q) {
                float x = fminf(sacc[nf][q], 60.f);
                float t = f_ex2(x * 1.44269504f);
                float u = f_lg2(1.0f + t);
                float ww = 0.69314718f * u * f_rcp(1.0f + f_ex2(-SILU_SCALE * u));
                int gi = gi0 + ((q >> 1) << 3);
                int gjj = gj + (q & 1);
                if ((diag && gjj > gi) || ww < sink) ww = 0.f;
                w[q] = ww;
            }
            rs0 += w[0] + w[1];
            rs1 += w[2] + w[3];
            uint2 s0 = { f2tf(w[0]), f2tf(w[1]) };
            uint2 s1 = { f2tf(w[2]), f2tf(w[3]) };
            *(uint2*)&Ws[li0 * APITCH + ljc]       = s0;
            *(uint2*)&Ws[(li0 + 8) * APITCH + ljc] = s1;
        }
        __syncthreads();

        if (kt < qt) ISSUE_TILES(kt + 1, b ^ 1);

#pragma unroll
        for (int ks = 0; ks < 8; ++ks) {
            uint32_t af[4], bf[4][2];
            const uint32_t* ap = &Ws[li0 * APITCH + ks * 8 + tg];
            af[0] = ap[0]; af[1] = ap[8 * APITCH];
            af[2] = ap[4]; af[3] = ap[8 * APITCH + 4];
#pragma unroll
            for (int nf = 0; nf < 4; ++nf) {
                const uint32_t* bp = &Vts[(wn * 32 + nf * 8 + g) * APITCH + ks * 8 + tg];
                bf[nf][0] = bp[0]; bf[nf][1] = bp[4];
            }
#pragma unroll
            for (int nf = 0; nf < 4; ++nf)
                mma_tf32(oacc[nf], af, bf[nf]);
        }
    }
#undef ISSUE_TILES

    __syncthreads();
    rs0 += __shfl_xor_sync(0xffffffffu, rs0, 1);
    rs0 += __shfl_xor_sync(0xffffffffu, rs0, 2);
    rs1 += __shfl_xor_sync(0xffffffffu, rs1, 1);
    rs1 += __shfl_xor_sync(0xffffffffu, rs1, 2);
    if (tg == 0) {
        RSm[wid * 16 + g]     = rs0;
        RSm[wid * 16 + 8 + g] = rs1;
    }
    __syncthreads();
    if (tid < 64)
        Tot[tid] = RSm[(tid >> 4) * 16 + (tid & 15)]
                 + RSm[((tid >> 4) + 4) * 16 + (tid & 15)] + sink + 1e-6f;
    __syncthreads();

    float invT0 = 1.0f / Tot[li0];
    float invT1 = 1.0f / Tot[li0 + 8];
#pragma unroll
    for (int nf = 0; nf < 4; ++nf) {
        int dloc = wn * 32 + nf * 8 + 2 * tg;
        float vn0 = v_nulls[head * DH + dloc];
        float vn1 = v_nulls[head * DH + dloc + 1];
        // tf32-rounded so the O-projection can cp.async raw bits
        uint2 o0 = { f2tf((oacc[nf][0] + sink * vn0) * invT0),
                     f2tf((oacc[nf][1] + sink * vn1) * invT0) };
        uint2 o1 = { f2tf((oacc[nf][2] + sink * vn0) * invT1),
                     f2tf((oacc[nf][3] + sink * vn1) * invT1) };
        *(uint2*)&g_OUT[(size_t)(qt * 64 + li0) * QDIM + head * DH + dloc]     = o0;
        *(uint2*)&g_OUT[(size_t)(qt * 64 + li0 + 8) * QDIM + head * DH + dloc] = o1;
    }
}

// ---------------------------------------------------------------------------
// Final reduce: Y = 0.25 * (sum of 4 K-split partials + sum_br bias)
// ---------------------------------------------------------------------------
__global__ __launch_bounds__(256)
void reduce_out_kernel(const float* __restrict__ part, const float* __restrict__ wob,
                       float* __restrict__ out)
{
    int idx = blockIdx.x * 256 + threadIdx.x;
    int d = idx & (DMODEL - 1);
    float s = part[idx] + part[idx + 1048576] + part[idx + 2097152] + part[idx + 3145728];
    float b = wob[d] + wob[DMODEL + d] + wob[2 * DMODEL + d] + wob[3 * DMODEL + d];
    out[idx] = 0.25f * (s + b);
}

// ---------------------------------------------------------------------------
extern "C" void kernel_launch(void* const* d_in, const int* in_sizes, int n_in,
                              void* d_out, int out_size)
{
    const float* X        = (const float*)d_in[0];
    const float* W_Q      = (const float*)d_in[1];
    const float* b_Q      = (const float*)d_in[2];
    const float* W_K      = (const float*)d_in[3];
    const float* b_K      = (const float*)d_in[4];
    const float* W_V      = (const float*)d_in[5];
    const float* b_V      = (const float*)d_in[6];
    const float* sinks    = (const float*)d_in[7];
    const float* v_nulls  = (const float*)d_in[8];
    const float* W_O      = (const float*)d_in[9];
    const float* W_O_bias = (const float*)d_in[10];
    float* out = (float*)d_out;

    float *Qp, *Kp, *Vtp, *PARTp;
    cudaGetSymbolAddress((void**)&Qp,    g_Q);
    cudaGetSymbolAddress((void**)&Kp,    g_K);
    cudaGetSymbolAddress((void**)&Vtp,   g_Vt);
    cudaGetSymbolAddress((void**)&PARTp, g_part);

    cudaFuncSetAttribute(gemm_qkv, cudaFuncAttributeMaxDynamicSharedMemorySize, GEMM_SMEM_BYTES);
    cudaFuncSetAttribute(gemm_tc_splitk, cudaFuncAttributeMaxDynamicSharedMemorySize, GEMM_SMEM_BYTES);
    cudaFuncSetAttribute(attn_tc_kernel, cudaFuncAttributeMaxDynamicSharedMemorySize, ATTN_SMEM_BYTES);

    // tf32 pre-rounding of X and all weights
    preround_all<<<dim3(256, 5), 256>>>(X, W_Q, W_K, W_V, W_O);
    // fused Q/K/V projections (V written transposed + tf32-rounded)
    gemm_qkv<<<dim3(48, 8, 1), 256, GEMM_SMEM_BYTES>>>(b_Q, b_K, b_V, Qp, Kp, Vtp);
    // RoPE + key_self folding + tf32 rounding of Q and K
    rope_kernel<<<10240, 256>>>(Qp, Kp);
    // pipelined tensor-core attention
    attn_tc_kernel<<<dim3(16, 64), 256, ATTN_SMEM_BYTES>>>(sinks, v_nulls);
    // output projection, split-K=4
    gemm_tc_splitk<<<dim3(8, 8, 4), 256, GEMM_SMEM_BYTES>>>(PARTp, 1024);
    reduce_out_kernel<<<4096, 256>>>(PARTp, W_O_bias, out);
}

// round 9
// speedup vs baseline: 3.9241x; 1.1936x over previous
#include <cuda_runtime.h>
#include <cuda_fp16.h>
#include <math.h>
#include <stdint.h>

#define T_LEN   1024
#define DMODEL  1024
#define QDIM    4096
#define HQ      64
#define HK      16
#define DH      64
#define SILU_SCALE 1.8137993642342178f   /* pi / sqrt(3) */
#define ATTN_SCALE 0.125f                /* DH^-0.5 */

static __device__ float  g_Q[T_LEN * QDIM];        // fp32 Q (pre-rope)
static __device__ float  g_K[T_LEN * DMODEL];      // fp32 K (pre-rope)
static __device__ __half g_Qh[T_LEN * QDIM];       // fp16 Q (post-rope)
static __device__ __half g_Kh[T_LEN * DMODEL];     // fp16 K (post-rope, prescaled)
static __device__ __half g_Vth[DMODEL * T_LEN];    // fp16 V^T: [d][t]
static __device__ float  g_OUT[T_LEN * QDIM];      // tf32-rounded attention output
static __device__ float  g_part[4 * T_LEN * DMODEL];
// tf32-prerounded GEMM operands (cp.async copies raw bits)
static __device__ float g_Xr[T_LEN * DMODEL];
static __device__ float g_WQr[DMODEL * QDIM];
static __device__ float g_WKr[DMODEL * DMODEL];
static __device__ float g_WVr[DMODEL * DMODEL];
static __device__ float g_WOr[QDIM * DMODEL];

// ===========================================================================
// helpers
// ===========================================================================
__device__ __forceinline__ float f_ex2(float x) { float y; asm("ex2.approx.ftz.f32 %0,%1;" : "=f"(y) : "f"(x)); return y; }
__device__ __forceinline__ float f_lg2(float x) { float y; asm("lg2.approx.ftz.f32 %0,%1;" : "=f"(y) : "f"(x)); return y; }
__device__ __forceinline__ float f_rcp(float x) { float y; asm("rcp.approx.ftz.f32 %0,%1;" : "=f"(y) : "f"(x)); return y; }
__device__ __forceinline__ uint32_t f2tf(float x) { uint32_t r; asm("cvt.rna.tf32.f32 %0,%1;" : "=r"(r) : "f"(x)); return r; }
__device__ __forceinline__ uint32_t smem_u32(const void* p) {
    uint32_t a;
    asm("{ .reg .u64 t; cvta.to.shared.u64 t, %1; cvt.u32.u64 %0, t; }" : "=r"(a) : "l"(p));
    return a;
}
__device__ __forceinline__ void cp_async16(uint32_t dst, const void* src) {
    asm volatile("cp.async.cg.shared.global [%0], [%1], 16;" :: "r"(dst), "l"(src));
}
#define CP_COMMIT() asm volatile("cp.async.commit_group;" ::: "memory")
#define CP_WAIT0()  asm volatile("cp.async.wait_group 0;"  ::: "memory")
#define CP_WAIT1()  asm volatile("cp.async.wait_group 1;"  ::: "memory")

__device__ __forceinline__ void mma_tf32(float* d, const uint32_t* a, const uint32_t* b) {
    asm volatile(
        "mma.sync.aligned.m16n8k8.row.col.f32.tf32.tf32.f32 "
        "{%0,%1,%2,%3}, {%4,%5,%6,%7}, {%8,%9}, {%0,%1,%2,%3};"
        : "+f"(d[0]), "+f"(d[1]), "+f"(d[2]), "+f"(d[3])
        : "r"(a[0]), "r"(a[1]), "r"(a[2]), "r"(a[3]), "r"(b[0]), "r"(b[1]));
}
__device__ __forceinline__ void mma_f16(float* d, const uint32_t* a, const uint32_t* b) {
    asm volatile(
        "mma.sync.aligned.m16n8k16.row.col.f32.f16.f16.f32 "
        "{%0,%1,%2,%3}, {%4,%5,%6,%7}, {%8,%9}, {%0,%1,%2,%3};"
        : "+f"(d[0]), "+f"(d[1]), "+f"(d[2]), "+f"(d[3])
        : "r"(a[0]), "r"(a[1]), "r"(a[2]), "r"(a[3]), "r"(b[0]), "r"(b[1]));
}
__device__ __forceinline__ uint32_t pack_h2(float a, float b) {
    __half2 h = __float22half2_rn(make_float2(a, b));
    return *(uint32_t*)&h;
}

// ---------------------------------------------------------------------------
// tf32 pre-rounding of GEMM operands
// ---------------------------------------------------------------------------
__global__ __launch_bounds__(256)
void preround_all(const float* __restrict__ X, const float* __restrict__ WQ,
                  const float* __restrict__ WK, const float* __restrict__ WV,
                  const float* __restrict__ WO)
{
    int z = blockIdx.y;
    const float* s; float* d; int n4;
    switch (z) {
        case 0:  s = X;  d = g_Xr;  n4 = (T_LEN * DMODEL) / 4;  break;
        case 1:  s = WQ; d = g_WQr; n4 = (DMODEL * QDIM) / 4;   break;
        case 2:  s = WK; d = g_WKr; n4 = (DMODEL * DMODEL) / 4; break;
        case 3:  s = WV; d = g_WVr; n4 = (DMODEL * DMODEL) / 4; break;
        default: s = WO; d = g_WOr; n4 = (QDIM * DMODEL) / 4;   break;
    }
    int stride = gridDim.x * 256;
    for (int i = blockIdx.x * 256 + threadIdx.x; i < n4; i += stride) {
        float4 v = ((const float4*)s)[i];
        float4 o;
        o.x = __uint_as_float(f2tf(v.x));
        o.y = __uint_as_float(f2tf(v.y));
        o.z = __uint_as_float(f2tf(v.z));
        o.w = __uint_as_float(f2tf(v.w));
        ((float4*)d)[i] = o;
    }
}

// ===========================================================================
// cp.async 3-stage pipelined tf32 GEMM (unchanged from R8)
// ===========================================================================
#define AS_PITCH 36
#define BS_PITCH 136
#define AS_WORDS (128 * AS_PITCH)
#define BS_WORDS (32 * BS_PITCH)
#define NSTAGE 3
#define STG_WORDS (AS_WORDS + BS_WORDS)
#define GEMM_SMEM_BYTES (NSTAGE * STG_WORDS * 4)

// OUTK: 0 = fp32 rows, 1 = fp16 V^T (transposed)
template <bool BIAS, int OUTK>
__device__ __forceinline__ void gemm_body(
    const float* __restrict__ A, const float* __restrict__ W,
    const float* __restrict__ bias, float* __restrict__ C, __half* __restrict__ Ch,
    int lda, int N, int m0, int n0, int kbase, int kLen)
{
    extern __shared__ uint32_t sm[];
    int tid  = threadIdx.x;
    int lane = tid & 31, wid = tid >> 5;
    int wm = wid & 3, wn = wid >> 2;
    int g = lane >> 2, tg = lane & 3;

    int arow = tid >> 3, ac4 = (tid & 7) * 4;
    int brow = tid >> 5, bc4 = (tid & 31) * 4;

    const float* Abase = &A[(size_t)(m0 + arow) * lda + kbase + ac4];
    const float* Bbase = &W[(size_t)(kbase + brow) * N + n0 + bc4];

    uint32_t aDst[NSTAGE], bDst[NSTAGE];
#pragma unroll
    for (int s = 0; s < NSTAGE; ++s) {
        aDst[s] = smem_u32(&sm[s * STG_WORDS + arow * AS_PITCH + ac4]);
        bDst[s] = smem_u32(&sm[s * STG_WORDS + AS_WORDS + brow * BS_PITCH + bc4]);
    }

#define ISSUE(it_)                                                                \
    do {                                                                          \
        int s_ = (it_) % NSTAGE;                                                  \
        _Pragma("unroll")                                                         \
        for (int i = 0; i < 4; ++i)                                               \
            cp_async16(aDst[s_] + i * 32 * AS_PITCH * 4,                          \
                       Abase + (size_t)32 * i * lda + (it_) * 32);                \
        _Pragma("unroll")                                                         \
        for (int i = 0; i < 4; ++i)                                               \
            cp_async16(bDst[s_] + i * 8 * BS_PITCH * 4,                           \
                       Bbase + (size_t)((it_) * 32 + 8 * i) * N);                 \
        CP_COMMIT();                                                              \
    } while (0)

    float acc[2][8][4];
#pragma unroll
    for (int mf = 0; mf < 2; ++mf)
#pragma unroll
        for (int nf = 0; nf < 8; ++nf)
#pragma unroll
            for (int q = 0; q < 4; ++q) acc[mf][nf][q] = 0.f;

    int NIT = kLen / 32;
    ISSUE(0);
    if (NIT > 1) ISSUE(1);

    for (int it = 0; it < NIT; ++it) {
        int s = it % NSTAGE;
        CP_WAIT1();
        __syncthreads();
        if (it + 2 < NIT) ISSUE(it + 2);

        const uint32_t* As = sm + s * STG_WORDS;
        const uint32_t* Bs = As + AS_WORDS;
#pragma unroll
        for (int ks = 0; ks < 4; ++ks) {
            uint32_t af[2][4], bf[8][2];
#pragma unroll
            for (int mf = 0; mf < 2; ++mf) {
                const uint32_t* p = &As[(wm * 32 + mf * 16 + g) * AS_PITCH + ks * 8 + tg];
                af[mf][0] = p[0];
                af[mf][1] = p[8 * AS_PITCH];
                af[mf][2] = p[4];
                af[mf][3] = p[8 * AS_PITCH + 4];
            }
#pragma unroll
            for (int nf = 0; nf < 8; ++nf) {
                const uint32_t* p = &Bs[(ks * 8 + tg) * BS_PITCH + wn * 64 + nf * 8 + g];
                bf[nf][0] = p[0];
                bf[nf][1] = p[4 * BS_PITCH];
            }
#pragma unroll
            for (int mf = 0; mf < 2; ++mf)
#pragma unroll
                for (int nf = 0; nf < 8; ++nf)
                    mma_tf32(acc[mf][nf], af[mf], bf[nf]);
        }
        __syncthreads();
    }
#undef ISSUE

#pragma unroll
    for (int mf = 0; mf < 2; ++mf) {
        int r0 = m0 + wm * 32 + mf * 16 + g;
#pragma unroll
        for (int nf = 0; nf < 8; ++nf) {
            int c = n0 + wn * 64 + nf * 8 + 2 * tg;
            float b0 = 0.f, b1 = 0.f;
            if (BIAS) { b0 = bias[c]; b1 = bias[c + 1]; }
            if (OUTK == 1) {
                // fp16 V^T layout [d][t]
                Ch[(size_t)c * T_LEN + r0]           = __float2half(acc[mf][nf][0] + b0);
                Ch[(size_t)(c + 1) * T_LEN + r0]     = __float2half(acc[mf][nf][1] + b1);
                Ch[(size_t)c * T_LEN + r0 + 8]       = __float2half(acc[mf][nf][2] + b0);
                Ch[(size_t)(c + 1) * T_LEN + r0 + 8] = __float2half(acc[mf][nf][3] + b1);
            } else {
                float2 v0 = { acc[mf][nf][0] + b0, acc[mf][nf][1] + b1 };
                float2 v1 = { acc[mf][nf][2] + b0, acc[mf][nf][3] + b1 };
                *(float2*)&C[(size_t)r0 * N + c]       = v0;
                *(float2*)&C[(size_t)(r0 + 8) * N + c] = v1;
            }
        }
    }
}

// Fused Q/K/V projections: 48 x-tiles (32 Q, 8 K, 8 V-transposed-fp16)
__global__ __launch_bounds__(256, 2)
void gemm_qkv(const float* __restrict__ b_Q, const float* __restrict__ b_K,
              const float* __restrict__ b_V,
              float* __restrict__ Qo, float* __restrict__ Ko)
{
    int bx = blockIdx.x, m0 = blockIdx.y * 128;
    if (bx < 32)
        gemm_body<true, 0>(g_Xr, g_WQr, b_Q, Qo, nullptr, DMODEL, QDIM, m0, bx * 128, 0, DMODEL);
    else if (bx < 40)
        gemm_body<true, 0>(g_Xr, g_WKr, b_K, Ko, nullptr, DMODEL, DMODEL, m0, (bx - 32) * 128, 0, DMODEL);
    else
        gemm_body<true, 1>(g_Xr, g_WVr, b_V, nullptr, g_Vth, DMODEL, DMODEL, m0, (bx - 40) * 128, 0, DMODEL);
}

__global__ __launch_bounds__(256, 2)
void gemm_tc_splitk(float* __restrict__ Cpart, int kPer)
{
    int z = blockIdx.z;
    gemm_body<false, 0>(g_OUT, g_WOr, nullptr, Cpart + (size_t)z * T_LEN * DMODEL, nullptr,
                        QDIM, DMODEL, blockIdx.y * 128, blockIdx.x * 128, z * kPer, kPer);
}

// ---------------------------------------------------------------------------
// RoPE + key_self/ATTN_SCALE folding; emits fp16 Q and K for attention.
// ---------------------------------------------------------------------------
__global__ __launch_bounds__(256)
void rope_kernel()
{
    int gw   = blockIdx.x * 8 + (threadIdx.x >> 5);
    int lane = threadIdx.x & 31;
    int slot = gw % (HQ + HK);
    int t    = gw / (HQ + HK);

    bool isK = (slot >= HQ);
    const float* ptr = isK ? (g_K + (size_t)t * DMODEL + (slot - HQ) * DH)
                           : (g_Q + (size_t)t * QDIM + slot * DH);
    __half* hptr = isK ? (g_Kh + (size_t)t * DMODEL + (slot - HQ) * DH)
                       : (g_Qh + (size_t)t * QDIM + slot * DH);

    float x1 = ptr[2 * lane];
    float x2 = ptr[2 * lane + 1];

    float inv = 1.0f / powf(10000.0f, (float)(2 * lane) / 64.0f);
    float fr  = (float)t * inv;
    float s, c;
    sincosf(fr, &s, &c);

    float o1 = x1 * c - x2 * s;
    float o2 = x1 * s + x2 * c;

    if (isK) {
        float nrm = x1 * x1 + x2 * x2;
#pragma unroll
        for (int off = 16; off; off >>= 1)
            nrm += __shfl_xor_sync(0xffffffffu, nrm, off);
        float ks  = fmaxf(nrm, 1e-6f);
        float scl = ATTN_SCALE * rsqrtf(ks);
        o1 *= scl;
        o2 *= scl;
    }
    hptr[lane]      = __float2half(o1);
    hptr[lane + 32] = __float2half(o2);
}

// ===========================================================================
// fp16 tensor-core attention: m16n8k16 HMMA, 46KB SMEM, prefetch hoisted to
// iteration top (overlaps the full S+activation+WV body).
// ===========================================================================
#define HPITCH 36                       // words (uint32) per 64-half row
#define HTILE_W (64 * HPITCH)
#define ATTN_SMEM_WORDS (5 * HTILE_W + 128 + 64)
#define ATTN_SMEM_BYTES (ATTN_SMEM_WORDS * 4)

__global__ __launch_bounds__(256)
void attn_tc_kernel(const float* __restrict__ sinks, const float* __restrict__ v_nulls)
{
    extern __shared__ uint32_t smu[];
    uint32_t* KsB[2]  = { smu,               smu + HTILE_W };
    uint32_t* VtsB[2] = { smu + 2 * HTILE_W, smu + 3 * HTILE_W };
    uint32_t* Ws      = smu + 4 * HTILE_W;
    float* RSm = (float*)(smu + 5 * HTILE_W);
    float* Tot = RSm + 128;

    int head = blockIdx.y;
    int qt   = (gridDim.x - 1) - blockIdx.x;   // heavy tiles first
    int kvh  = head & (HK - 1);
    int tid  = threadIdx.x;
    int lane = tid & 31, wid = tid >> 5;
    int wm = wid & 3, wn = wid >> 2;
    int g = lane >> 2, tg = lane & 3;
    float sink = sinks[head];

    // cp.async copy slots: thread handles rows crow, crow+32; 16B chunk cc
    int crow = tid >> 3, cc = tid & 7;
    uint32_t ksA[2], vtA[2];
#pragma unroll
    for (int b = 0; b < 2; ++b) {
        ksA[b] = smem_u32(&KsB[b][crow * HPITCH + cc * 4]);
        vtA[b] = smem_u32(&VtsB[b][crow * HPITCH + cc * 4]);
    }
    const __half* kSrc  = g_Kh + (size_t)crow * DMODEL + kvh * DH + cc * 8;
    const __half* vtSrc = g_Vth + (size_t)(kvh * DH + crow) * T_LEN + cc * 8;

#define ISSUE_TILES(kt_, b_)                                                     \
    do {                                                                         \
        cp_async16(ksA[b_],                     kSrc + (size_t)(kt_) * 64 * DMODEL); \
        cp_async16(ksA[b_] + 32 * HPITCH * 4,   kSrc + (size_t)((kt_) * 64 + 32) * DMODEL); \
        cp_async16(vtA[b_],                     vtSrc + (kt_) * 64);             \
        cp_async16(vtA[b_] + 32 * HPITCH * 4,   vtSrc + 32 * T_LEN + (kt_) * 64); \
        CP_COMMIT();                                                             \
    } while (0)

    ISSUE_TILES(0, 0);

    // stage Q (fp16) through Ws, then hoist A-fragments to registers
    {
        const uint32_t* qsrc = (const uint32_t*)g_Qh;
#pragma unroll
        for (int i = 0; i < 8; ++i) {
            int idx = tid + 256 * i;
            int r = idx >> 5, wc = idx & 31;
            Ws[r * HPITCH + wc] = qsrc[(size_t)(qt * 64 + r) * (QDIM / 2) + head * (DH / 2) + wc];
        }
    }
    __syncthreads();
    int li0 = wm * 16 + g;
    uint32_t afq[4][4];
    {
        const uint32_t* p0 = &Ws[li0 * HPITCH];
#pragma unroll
        for (int kk = 0; kk < 4; ++kk) {
            afq[kk][0] = p0[kk * 8 + tg];
            afq[kk][1] = p0[8 * HPITCH + kk * 8 + tg];
            afq[kk][2] = p0[kk * 8 + 4 + tg];
            afq[kk][3] = p0[8 * HPITCH + kk * 8 + 4 + tg];
        }
    }

    float oacc[4][4];
#pragma unroll
    for (int nf = 0; nf < 4; ++nf)
#pragma unroll
        for (int q = 0; q < 4; ++q) oacc[nf][q] = 0.f;
    float rs0 = 0.f, rs1 = 0.f;
    int gi0 = qt * 64 + li0;

    for (int kt = 0; kt <= qt; ++kt) {
        int b = kt & 1;
        CP_WAIT0();
        __syncthreads();   // K[b]/Vt[b] visible; all warps done with WV(kt-1)

        // prefetch kt+1 immediately (overlaps S + activation + WV below)
        if (kt < qt) ISSUE_TILES(kt + 1, b ^ 1);

        const uint32_t* Ks  = KsB[b];
        const uint32_t* Vts = VtsB[b];

        // ---- S = Q @ K^T (fp16, 4 k-chunks of 16)
        float sacc[4][4];
#pragma unroll
        for (int nf = 0; nf < 4; ++nf)
#pragma unroll
            for (int q = 0; q < 4; ++q) sacc[nf][q] = 0.f;

#pragma unroll
        for (int kk = 0; kk < 4; ++kk) {
            uint32_t bf[4][2];
#pragma unroll
            for (int nf = 0; nf < 4; ++nf) {
                const uint32_t* bp = &Ks[(wn * 32 + nf * 8 + g) * HPITCH + kk * 8 + tg];
                bf[nf][0] = bp[0]; bf[nf][1] = bp[4];
            }
#pragma unroll
            for (int nf = 0; nf < 4; ++nf)
                mma_f16(sacc[nf], afq[kk], bf[nf]);
        }

        // ---- activation in registers -> Ws (fp16 pairs)
        bool diag = (kt == qt);
#pragma unroll
        for (int nf = 0; nf < 4; ++nf) {
            int ljc = wn * 32 + nf * 8 + 2 * tg;
            int gj  = kt * 64 + ljc;
            float w[4];
#pragma unroll
            for (int q = 0; q < 4; ++q) {
                float x = fminf(sacc[nf][q], 60.f);
                float t = f_ex2(x * 1.44269504f);
                float u = f_lg2(1.0f + t);
                float ww = 0.69314718f * u * f_rcp(1.0f + f_ex2(-SILU_SCALE * u));
                int gi = gi0 + ((q >> 1) << 3);
                int gjj = gj + (q & 1);
                if ((diag && gjj > gi) || ww < sink) ww = 0.f;
                w[q] = ww;
            }
            rs0 += w[0] + w[1];
            rs1 += w[2] + w[3];
            int wc = wn * 16 + nf * 4 + tg;
            Ws[li0 * HPITCH + wc]       = pack_h2(w[0], w[1]);
            Ws[(li0 + 8) * HPITCH + wc] = pack_h2(w[2], w[3]);
        }
        __syncthreads();   // Ws visible to all warps

        // ---- O += W @ V (fp16, 4 k-chunks of 16 keys)
#pragma unroll
        for (int kk = 0; kk < 4; ++kk) {
            uint32_t af[4], bf[4][2];
            const uint32_t* ap = &Ws[li0 * HPITCH + kk * 8 + tg];
            af[0] = ap[0];
            af[1] = ap[8 * HPITCH];
            af[2] = ap[4];
            af[3] = ap[8 * HPITCH + 4];
#pragma unroll
            for (int nf = 0; nf < 4; ++nf) {
                const uint32_t* bp = &Vts[(wn * 32 + nf * 8 + g) * HPITCH + kk * 8 + tg];
                bf[nf][0] = bp[0]; bf[nf][1] = bp[4];
            }
#pragma unroll
            for (int nf = 0; nf < 4; ++nf)
                mma_f16(oacc[nf], af, bf[nf]);
        }
    }
#undef ISSUE_TILES

    // ---- row-sum reduction
    __syncthreads();
    rs0 += __shfl_xor_sync(0xffffffffu, rs0, 1);
    rs0 += __shfl_xor_sync(0xffffffffu, rs0, 2);
    rs1 += __shfl_xor_sync(0xffffffffu, rs1, 1);
    rs1 += __shfl_xor_sync(0xffffffffu, rs1, 2);
    if (tg == 0) {
        RSm[wid * 16 + g]     = rs0;
        RSm[wid * 16 + 8 + g] = rs1;
    }
    __syncthreads();
    if (tid < 64)
        Tot[tid] = RSm[(tid >> 4) * 16 + (tid & 15)]
                 + RSm[((tid >> 4) + 4) * 16 + (tid & 15)] + sink + 1e-6f;
    __syncthreads();

    // ---- epilogue (tf32-rounded fp32 for the O-projection's cp.async path)
    float invT0 = 1.0f / Tot[li0];
    float invT1 = 1.0f / Tot[li0 + 8];
#pragma unroll
    for (int nf = 0; nf < 4; ++nf) {
        int dloc = wn * 32 + nf * 8 + 2 * tg;
        float vn0 = v_nulls[head * DH + dloc];
        float vn1 = v_nulls[head * DH + dloc + 1];
        uint2 o0 = { f2tf((oacc[nf][0] + sink * vn0) * invT0),
                     f2tf((oacc[nf][1] + sink * vn1) * invT0) };
        uint2 o1 = { f2tf((oacc[nf][2] + sink * vn0) * invT1),
                     f2tf((oacc[nf][3] + sink * vn1) * invT1) };
        *(uint2*)&g_OUT[(size_t)(qt * 64 + li0) * QDIM + head * DH + dloc]     = o0;
        *(uint2*)&g_OUT[(size_t)(qt * 64 + li0 + 8) * QDIM + head * DH + dloc] = o1;
    }
}

// ---------------------------------------------------------------------------
// Final reduce: Y = 0.25 * (sum of 4 K-split partials + sum_br bias)
// ---------------------------------------------------------------------------
__global__ __launch_bounds__(256)
void reduce_out_kernel(const float* __restrict__ part, const float* __restrict__ wob,
                       float* __restrict__ out)
{
    int idx = blockIdx.x * 256 + threadIdx.x;
    int d = idx & (DMODEL - 1);
    float s = part[idx] + part[idx + 1048576] + part[idx + 2097152] + part[idx + 3145728];
    float b = wob[d] + wob[DMODEL + d] + wob[2 * DMODEL + d] + wob[3 * DMODEL + d];
    out[idx] = 0.25f * (s + b);
}

// ---------------------------------------------------------------------------
extern "C" void kernel_launch(void* const* d_in, const int* in_sizes, int n_in,
                              void* d_out, int out_size)
{
    const float* X        = (const float*)d_in[0];
    const float* W_Q      = (const float*)d_in[1];
    const float* b_Q      = (const float*)d_in[2];
    const float* W_K      = (const float*)d_in[3];
    const float* b_K      = (const float*)d_in[4];
    const float* W_V      = (const float*)d_in[5];
    const float* b_V      = (const float*)d_in[6];
    const float* sinks    = (const float*)d_in[7];
    const float* v_nulls  = (const float*)d_in[8];
    const float* W_O      = (const float*)d_in[9];
    const float* W_O_bias = (const float*)d_in[10];
    float* out = (float*)d_out;

    float *Qp, *Kp, *PARTp;
    cudaGetSymbolAddress((void**)&Qp,    g_Q);
    cudaGetSymbolAddress((void**)&Kp,    g_K);
    cudaGetSymbolAddress((void**)&PARTp, g_part);

    cudaFuncSetAttribute(gemm_qkv, cudaFuncAttributeMaxDynamicSharedMemorySize, GEMM_SMEM_BYTES);
    cudaFuncSetAttribute(gemm_tc_splitk, cudaFuncAttributeMaxDynamicSharedMemorySize, GEMM_SMEM_BYTES);
    cudaFuncSetAttribute(attn_tc_kernel, cudaFuncAttributeMaxDynamicSharedMemorySize, ATTN_SMEM_BYTES);

    // tf32 pre-rounding of X and all weights
    preround_all<<<dim3(256, 5), 256>>>(X, W_Q, W_K, W_V, W_O);
    // fused Q/K/V projections (V written transposed fp16)
    gemm_qkv<<<dim3(48, 8, 1), 256, GEMM_SMEM_BYTES>>>(b_Q, b_K, b_V, Qp, Kp);
    // RoPE + key_self folding -> fp16 Q/K
    rope_kernel<<<10240, 256>>>();
    // fp16 tensor-core attention
    attn_tc_kernel<<<dim3(16, 64), 256, ATTN_SMEM_BYTES>>>(sinks, v_nulls);
    // output projection, split-K=4
    gemm_tc_splitk<<<dim3(8, 8, 4), 256, GEMM_SMEM_BYTES>>>(PARTp, 1024);
    reduce_out_kernel<<<4096, 256>>>(PARTp, W_O_bias, out);
}

// round 10
// speedup vs baseline: 4.4162x; 1.1254x over previous
#include <cuda_runtime.h>
#include <cuda_fp16.h>
#include <math.h>
#include <stdint.h>

#define T_LEN   1024
#define DMODEL  1024
#define QDIM    4096
#define HQ      64
#define HK      16
#define DH      64
#define SILU_SCALE 1.8137993642342178f   /* pi / sqrt(3) */
#define ATTN_SCALE 0.125f                /* DH^-0.5 */

static __device__ float  g_Q[T_LEN * QDIM];        // fp32 Q (pre-rope)
static __device__ float  g_K[T_LEN * DMODEL];      // fp32 K (pre-rope)
static __device__ __half g_Qh[T_LEN * QDIM];       // fp16 Q (post-rope)
static __device__ __half g_Kh[T_LEN * DMODEL];     // fp16 K (post-rope, prescaled)
static __device__ __half g_Vth[DMODEL * T_LEN];    // fp16 V^T: [d][t]
static __device__ __half g_OUTh[T_LEN * QDIM];     // fp16 attention output
static __device__ float  g_part[4 * T_LEN * DMODEL];
// fp16-converted GEMM operands (weights transposed to [N][K])
static __device__ __half g_Xh[T_LEN * DMODEL];
static __device__ __half g_WQt[QDIM * DMODEL];
static __device__ __half g_WKt[DMODEL * DMODEL];
static __device__ __half g_WVt[DMODEL * DMODEL];
static __device__ __half g_WOt[DMODEL * QDIM];

// ===========================================================================
// helpers
// ===========================================================================
__device__ __forceinline__ float f_ex2(float x) { float y; asm("ex2.approx.ftz.f32 %0,%1;" : "=f"(y) : "f"(x)); return y; }
__device__ __forceinline__ float f_lg2(float x) { float y; asm("lg2.approx.ftz.f32 %0,%1;" : "=f"(y) : "f"(x)); return y; }
__device__ __forceinline__ float f_rcp(float x) { float y; asm("rcp.approx.ftz.f32 %0,%1;" : "=f"(y) : "f"(x)); return y; }
__device__ __forceinline__ uint32_t smem_u32(const void* p) {
    uint32_t a;
    asm("{ .reg .u64 t; cvta.to.shared.u64 t, %1; cvt.u32.u64 %0, t; }" : "=r"(a) : "l"(p));
    return a;
}
__device__ __forceinline__ void cp_async16(uint32_t dst, const void* src) {
    asm volatile("cp.async.cg.shared.global [%0], [%1], 16;" :: "r"(dst), "l"(src));
}
#define CP_COMMIT() asm volatile("cp.async.commit_group;" ::: "memory")
#define CP_WAIT0()  asm volatile("cp.async.wait_group 0;"  ::: "memory")
#define CP_WAIT1()  asm volatile("cp.async.wait_group 1;"  ::: "memory")

__device__ __forceinline__ void mma_f16(float* d, const uint32_t* a, const uint32_t* b) {
    asm volatile(
        "mma.sync.aligned.m16n8k16.row.col.f32.f16.f16.f32 "
        "{%0,%1,%2,%3}, {%4,%5,%6,%7}, {%8,%9}, {%0,%1,%2,%3};"
        : "+f"(d[0]), "+f"(d[1]), "+f"(d[2]), "+f"(d[3])
        : "r"(a[0]), "r"(a[1]), "r"(a[2]), "r"(a[3]), "r"(b[0]), "r"(b[1]));
}
__device__ __forceinline__ uint32_t pack_h2(float a, float b) {
    __half2 h = __float22half2_rn(make_float2(a, b));
    return *(uint32_t*)&h;
}

// ---------------------------------------------------------------------------
// Convert X to fp16 (z=0) and transpose-convert weights to fp16 [N][K] (z>=1)
// ---------------------------------------------------------------------------
__global__ __launch_bounds__(256)
void convert_ops(const float* __restrict__ X, const float* __restrict__ WQ,
                 const float* __restrict__ WK, const float* __restrict__ WV,
                 const float* __restrict__ WO)
{
    int z = blockIdx.y;
    int tid = threadIdx.x;

    if (z == 0) {
        int i = blockIdx.x * 256 + tid;
        if (i < (T_LEN * DMODEL) / 4) {
            float4 v = ((const float4*)X)[i];
            uint2 o = { pack_h2(v.x, v.y), pack_h2(v.z, v.w) };
            ((uint2*)g_Xh)[i] = o;
        }
        return;
    }

    const float* src; __half* dst; int Kd, Nd;
    switch (z) {
        case 1:  src = WQ; dst = g_WQt; Kd = DMODEL; Nd = QDIM;   break;
        case 2:  src = WK; dst = g_WKt; Kd = DMODEL; Nd = DMODEL; break;
        case 3:  src = WV; dst = g_WVt; Kd = DMODEL; Nd = DMODEL; break;
        default: src = WO; dst = g_WOt; Kd = QDIM;   Nd = DMODEL; break;
    }
    int ntx = Nd >> 5;                      // col tiles
    int tiles = ntx * (Kd >> 5);
    int bx = blockIdx.x;
    if (bx >= tiles) return;
    int tx = bx % ntx, ty = bx / ntx;       // tile col (n), tile row (k)

    __shared__ __half tile[32][33];
    int r = tid >> 5, c = tid & 31;
#pragma unroll
    for (int i = 0; i < 4; ++i) {
        int row = r + i * 8;
        tile[row][c] = __float2half(src[(size_t)(ty * 32 + row) * Nd + tx * 32 + c]);
    }
    __syncthreads();
#pragma unroll
    for (int i = 0; i < 4; ++i) {
        int row = r + i * 8;                // output n-row within tile
        dst[(size_t)(tx * 32 + row) * Kd + ty * 32 + c] = tile[c][row];
    }
}

// ===========================================================================
// fp16 cp.async 3-stage pipelined GEMM: 128x128 tile, BK=32, 8 warps (4m x 2n)
// A [M][K] fp16 k-contiguous, Bt [N][K] fp16 k-contiguous. 60KB SMEM.
// ===========================================================================
#define FP_PITCH 20                       // words per 32-half row (16 data + 4 pad)
#define FP_TILE_WORDS (128 * FP_PITCH)
#define NSTAGE 3
#define FP_STG_WORDS (2 * FP_TILE_WORDS)
#define GEMM_SMEM_BYTES (NSTAGE * FP_STG_WORDS * 4)

// OUTK: 0 = fp32 rows, 1 = fp16 transposed (V^T)
template <bool BIAS, int OUTK>
__device__ __forceinline__ void gemm_body(
    const __half* __restrict__ A, const __half* __restrict__ Bt,
    const float* __restrict__ bias, float* __restrict__ C, __half* __restrict__ Ch,
    int lda, int ldb, int N, int m0, int n0, int kbase, int kLen)
{
    extern __shared__ uint32_t sm[];
    int tid  = threadIdx.x;
    int lane = tid & 31, wid = tid >> 5;
    int wm = wid & 3, wn = wid >> 2;
    int g = lane >> 2, tg = lane & 3;

    int crow = tid >> 1, cch = tid & 1;    // copy: row 0..127, chunk 0..1 (of 4)

    const __half* Abase = &A[(size_t)(m0 + crow) * lda + kbase + cch * 8];
    const __half* Bbase = &Bt[(size_t)(n0 + crow) * ldb + kbase + cch * 8];

    uint32_t aDst[NSTAGE], bDst[NSTAGE];
#pragma unroll
    for (int s = 0; s < NSTAGE; ++s) {
        aDst[s] = smem_u32(&sm[s * FP_STG_WORDS + crow * FP_PITCH + cch * 4]);
        bDst[s] = smem_u32(&sm[s * FP_STG_WORDS + FP_TILE_WORDS + crow * FP_PITCH + cch * 4]);
    }

#define ISSUE(it_)                                                \
    do {                                                          \
        int s_ = (it_) % NSTAGE;                                  \
        cp_async16(aDst[s_],      Abase + (it_) * 32);            \
        cp_async16(aDst[s_] + 32, Abase + (it_) * 32 + 16);       \
        cp_async16(bDst[s_],      Bbase + (it_) * 32);            \
        cp_async16(bDst[s_] + 32, Bbase + (it_) * 32 + 16);       \
        CP_COMMIT();                                              \
    } while (0)

    float acc[2][8][4];
#pragma unroll
    for (int mf = 0; mf < 2; ++mf)
#pragma unroll
        for (int nf = 0; nf < 8; ++nf)
#pragma unroll
            for (int q = 0; q < 4; ++q) acc[mf][nf][q] = 0.f;

    int NIT = kLen / 32;
    ISSUE(0);
    if (NIT > 1) ISSUE(1);

    for (int it = 0; it < NIT; ++it) {
        int s = it % NSTAGE;
        CP_WAIT1();
        __syncthreads();
        if (it + 2 < NIT) ISSUE(it + 2);

        const uint32_t* As = sm + s * FP_STG_WORDS;
        const uint32_t* Bs = As + FP_TILE_WORDS;
#pragma unroll
        for (int kk = 0; kk < 2; ++kk) {
            uint32_t af[2][4], bf[8][2];
#pragma unroll
            for (int mf = 0; mf < 2; ++mf) {
                const uint32_t* p = &As[(wm * 32 + mf * 16 + g) * FP_PITCH + kk * 8 + tg];
                af[mf][0] = p[0];
                af[mf][1] = p[8 * FP_PITCH];
                af[mf][2] = p[4];
                af[mf][3] = p[8 * FP_PITCH + 4];
            }
#pragma unroll
            for (int nf = 0; nf < 8; ++nf) {
                const uint32_t* p = &Bs[(wn * 64 + nf * 8 + g) * FP_PITCH + kk * 8 + tg];
                bf[nf][0] = p[0];
                bf[nf][1] = p[4];
            }
#pragma unroll
            for (int mf = 0; mf < 2; ++mf)
#pragma unroll
                for (int nf = 0; nf < 8; ++nf)
                    mma_f16(acc[mf][nf], af[mf], bf[nf]);
        }
        __syncthreads();
    }
#undef ISSUE

#pragma unroll
    for (int mf = 0; mf < 2; ++mf) {
        int r0 = m0 + wm * 32 + mf * 16 + g;
#pragma unroll
        for (int nf = 0; nf < 8; ++nf) {
            int c = n0 + wn * 64 + nf * 8 + 2 * tg;
            float b0 = 0.f, b1 = 0.f;
            if (BIAS) { b0 = bias[c]; b1 = bias[c + 1]; }
            if (OUTK == 1) {
                Ch[(size_t)c * T_LEN + r0]           = __float2half(acc[mf][nf][0] + b0);
                Ch[(size_t)(c + 1) * T_LEN + r0]     = __float2half(acc[mf][nf][1] + b1);
                Ch[(size_t)c * T_LEN + r0 + 8]       = __float2half(acc[mf][nf][2] + b0);
                Ch[(size_t)(c + 1) * T_LEN + r0 + 8] = __float2half(acc[mf][nf][3] + b1);
            } else {
                float2 v0 = { acc[mf][nf][0] + b0, acc[mf][nf][1] + b1 };
                float2 v1 = { acc[mf][nf][2] + b0, acc[mf][nf][3] + b1 };
                *(float2*)&C[(size_t)r0 * N + c]       = v0;
                *(float2*)&C[(size_t)(r0 + 8) * N + c] = v1;
            }
        }
    }
}

// Fused Q/K/V projections: 48 x-tiles (32 Q, 8 K, 8 V-transposed-fp16)
__global__ __launch_bounds__(256, 2)
void gemm_qkv(const float* __restrict__ b_Q, const float* __restrict__ b_K,
              const float* __restrict__ b_V,
              float* __restrict__ Qo, float* __restrict__ Ko)
{
    int bx = blockIdx.x, m0 = blockIdx.y * 128;
    if (bx < 32)
        gemm_body<true, 0>(g_Xh, g_WQt, b_Q, Qo, nullptr, DMODEL, DMODEL, QDIM, m0, bx * 128, 0, DMODEL);
    else if (bx < 40)
        gemm_body<true, 0>(g_Xh, g_WKt, b_K, Ko, nullptr, DMODEL, DMODEL, DMODEL, m0, (bx - 32) * 128, 0, DMODEL);
    else
        gemm_body<true, 1>(g_Xh, g_WVt, b_V, nullptr, g_Vth, DMODEL, DMODEL, DMODEL, m0, (bx - 40) * 128, 0, DMODEL);
}

__global__ __launch_bounds__(256, 2)
void gemm_tc_splitk(float* __restrict__ Cpart, int kPer)
{
    int z = blockIdx.z;
    gemm_body<false, 0>(g_OUTh, g_WOt, nullptr, Cpart + (size_t)z * T_LEN * DMODEL, nullptr,
                        QDIM, QDIM, DMODEL, blockIdx.y * 128, blockIdx.x * 128, z * kPer, kPer);
}

// ---------------------------------------------------------------------------
// RoPE + key_self/ATTN_SCALE folding; emits fp16 Q and K for attention.
// ---------------------------------------------------------------------------
__global__ __launch_bounds__(256)
void rope_kernel()
{
    int gw   = blockIdx.x * 8 + (threadIdx.x >> 5);
    int lane = threadIdx.x & 31;
    int slot = gw % (HQ + HK);
    int t    = gw / (HQ + HK);

    bool isK = (slot >= HQ);
    const float* ptr = isK ? (g_K + (size_t)t * DMODEL + (slot - HQ) * DH)
                           : (g_Q + (size_t)t * QDIM + slot * DH);
    __half* hptr = isK ? (g_Kh + (size_t)t * DMODEL + (slot - HQ) * DH)
                       : (g_Qh + (size_t)t * QDIM + slot * DH);

    float x1 = ptr[2 * lane];
    float x2 = ptr[2 * lane + 1];

    float inv = 1.0f / powf(10000.0f, (float)(2 * lane) / 64.0f);
    float fr  = (float)t * inv;
    float s, c;
    sincosf(fr, &s, &c);

    float o1 = x1 * c - x2 * s;
    float o2 = x1 * s + x2 * c;

    if (isK) {
        float nrm = x1 * x1 + x2 * x2;
#pragma unroll
        for (int off = 16; off; off >>= 1)
            nrm += __shfl_xor_sync(0xffffffffu, nrm, off);
        float ks  = fmaxf(nrm, 1e-6f);
        float scl = ATTN_SCALE * rsqrtf(ks);
        o1 *= scl;
        o2 *= scl;
    }
    hptr[lane]      = __float2half(o1);
    hptr[lane + 32] = __float2half(o2);
}

// ===========================================================================
// fp16 tensor-core attention (R9, unchanged except fp16 OUT epilogue)
// ===========================================================================
#define HPITCH 36
#define HTILE_W (64 * HPITCH)
#define ATTN_SMEM_WORDS (5 * HTILE_W + 128 + 64)
#define ATTN_SMEM_BYTES (ATTN_SMEM_WORDS * 4)

__global__ __launch_bounds__(256)
void attn_tc_kernel(const float* __restrict__ sinks, const float* __restrict__ v_nulls)
{
    extern __shared__ uint32_t smu[];
    uint32_t* KsB[2]  = { smu,               smu + HTILE_W };
    uint32_t* VtsB[2] = { smu + 2 * HTILE_W, smu + 3 * HTILE_W };
    uint32_t* Ws      = smu + 4 * HTILE_W;
    float* RSm = (float*)(smu + 5 * HTILE_W);
    float* Tot = RSm + 128;

    int head = blockIdx.y;
    int qt   = (gridDim.x - 1) - blockIdx.x;   // heavy tiles first
    int kvh  = head & (HK - 1);
    int tid  = threadIdx.x;
    int lane = tid & 31, wid = tid >> 5;
    int wm = wid & 3, wn = wid >> 2;
    int g = lane >> 2, tg = lane & 3;
    float sink = sinks[head];

    int crow = tid >> 3, cc = tid & 7;
    uint32_t ksA[2], vtA[2];
#pragma unroll
    for (int b = 0; b < 2; ++b) {
        ksA[b] = smem_u32(&KsB[b][crow * HPITCH + cc * 4]);
        vtA[b] = smem_u32(&VtsB[b][crow * HPITCH + cc * 4]);
    }
    const __half* kSrc  = g_Kh + (size_t)crow * DMODEL + kvh * DH + cc * 8;
    const __half* vtSrc = g_Vth + (size_t)(kvh * DH + crow) * T_LEN + cc * 8;

#define ISSUE_TILES(kt_, b_)                                                     \
    do {                                                                         \
        cp_async16(ksA[b_],                     kSrc + (size_t)(kt_) * 64 * DMODEL); \
        cp_async16(ksA[b_] + 32 * HPITCH * 4,   kSrc + (size_t)((kt_) * 64 + 32) * DMODEL); \
        cp_async16(vtA[b_],                     vtSrc + (kt_) * 64);             \
        cp_async16(vtA[b_] + 32 * HPITCH * 4,   vtSrc + 32 * T_LEN + (kt_) * 64); \
        CP_COMMIT();                                                             \
    } while (0)

    ISSUE_TILES(0, 0);

    {
        const uint32_t* qsrc = (const uint32_t*)g_Qh;
#pragma unroll
        for (int i = 0; i < 8; ++i) {
            int idx = tid + 256 * i;
            int r = idx >> 5, wc = idx & 31;
            Ws[r * HPITCH + wc] = qsrc[(size_t)(qt * 64 + r) * (QDIM / 2) + head * (DH / 2) + wc];
        }
    }
    __syncthreads();
    int li0 = wm * 16 + g;
    uint32_t afq[4][4];
    {
        const uint32_t* p0 = &Ws[li0 * HPITCH];
#pragma unroll
        for (int kk = 0; kk < 4; ++kk) {
            afq[kk][0] = p0[kk * 8 + tg];
            afq[kk][1] = p0[8 * HPITCH + kk * 8 + tg];
            afq[kk][2] = p0[kk * 8 + 4 + tg];
            afq[kk][3] = p0[8 * HPITCH + kk * 8 + 4 + tg];
        }
    }

    float oacc[4][4];
#pragma unroll
    for (int nf = 0; nf < 4; ++nf)
#pragma unroll
        for (int q = 0; q < 4; ++q) oacc[nf][q] = 0.f;
    float rs0 = 0.f, rs1 = 0.f;
    int gi0 = qt * 64 + li0;

    for (int kt = 0; kt <= qt; ++kt) {
        int b = kt & 1;
        CP_WAIT0();
        __syncthreads();

        if (kt < qt) ISSUE_TILES(kt + 1, b ^ 1);

        const uint32_t* Ks  = KsB[b];
        const uint32_t* Vts = VtsB[b];

        float sacc[4][4];
#pragma unroll
        for (int nf = 0; nf < 4; ++nf)
#pragma unroll
            for (int q = 0; q < 4; ++q) sacc[nf][q] = 0.f;

#pragma unroll
        for (int kk = 0; kk < 4; ++kk) {
            uint32_t bf[4][2];
#pragma unroll
            for (int nf = 0; nf < 4; ++nf) {
                const uint32_t* bp = &Ks[(wn * 32 + nf * 8 + g) * HPITCH + kk * 8 + tg];
                bf[nf][0] = bp[0]; bf[nf][1] = bp[4];
            }
#pragma unroll
            for (int nf = 0; nf < 4; ++nf)
                mma_f16(sacc[nf], afq[kk], bf[nf]);
        }

        bool diag = (kt == qt);
#pragma unroll
        for (int nf = 0; nf < 4; ++nf) {
            int ljc = wn * 32 + nf * 8 + 2 * tg;
            int gj  = kt * 64 + ljc;
            float w[4];
#pragma unroll
            for (int q = 0; q < 4; ++q) {
                float x = fminf(sacc[nf][q], 60.f);
                float t = f_ex2(x * 1.44269504f);
                float u = f_lg2(1.0f + t);
                float ww = 0.69314718f * u * f_rcp(1.0f + f_ex2(-SILU_SCALE * u));
                int gi = gi0 + ((q >> 1) << 3);
                int gjj = gj + (q & 1);
                if ((diag && gjj > gi) || ww < sink) ww = 0.f;
                w[q] = ww;
            }
            rs0 += w[0] + w[1];
            rs1 += w[2] + w[3];
            int wc = wn * 16 + nf * 4 + tg;
            Ws[li0 * HPITCH + wc]       = pack_h2(w[0], w[1]);
            Ws[(li0 + 8) * HPITCH + wc] = pack_h2(w[2], w[3]);
        }
        __syncthreads();

#pragma unroll
        for (int kk = 0; kk < 4; ++kk) {
            uint32_t af[4], bf[4][2];
            const uint32_t* ap = &Ws[li0 * HPITCH + kk * 8 + tg];
            af[0] = ap[0];
            af[1] = ap[8 * HPITCH];
            af[2] = ap[4];
            af[3] = ap[8 * HPITCH + 4];
#pragma unroll
            for (int nf = 0; nf < 4; ++nf) {
                const uint32_t* bp = &Vts[(wn * 32 + nf * 8 + g) * HPITCH + kk * 8 + tg];
                bf[nf][0] = bp[0]; bf[nf][1] = bp[4];
            }
#pragma unroll
            for (int nf = 0; nf < 4; ++nf)
                mma_f16(oacc[nf], af, bf[nf]);
        }
    }
#undef ISSUE_TILES

    __syncthreads();
    rs0 += __shfl_xor_sync(0xffffffffu, rs0, 1);
    rs0 += __shfl_xor_sync(0xffffffffu, rs0, 2);
    rs1 += __shfl_xor_sync(0xffffffffu, rs1, 1);
    rs1 += __shfl_xor_sync(0xffffffffu, rs1, 2);
    if (tg == 0) {
        RSm[wid * 16 + g]     = rs0;
        RSm[wid * 16 + 8 + g] = rs1;
    }
    __syncthreads();
    if (tid < 64)
        Tot[tid] = RSm[(tid >> 4) * 16 + (tid & 15)]
                 + RSm[((tid >> 4) + 4) * 16 + (tid & 15)] + sink + 1e-6f;
    __syncthreads();

    float invT0 = 1.0f / Tot[li0];
    float invT1 = 1.0f / Tot[li0 + 8];
#pragma unroll
    for (int nf = 0; nf < 4; ++nf) {
        int dloc = wn * 32 + nf * 8 + 2 * tg;
        float vn0 = v_nulls[head * DH + dloc];
        float vn1 = v_nulls[head * DH + dloc + 1];
        uint32_t o0 = pack_h2((oacc[nf][0] + sink * vn0) * invT0,
                              (oacc[nf][1] + sink * vn1) * invT0);
        uint32_t o1 = pack_h2((oacc[nf][2] + sink * vn0) * invT1,
                              (oacc[nf][3] + sink * vn1) * invT1);
        *(uint32_t*)&g_OUTh[(size_t)(qt * 64 + li0) * QDIM + head * DH + dloc]     = o0;
        *(uint32_t*)&g_OUTh[(size_t)(qt * 64 + li0 + 8) * QDIM + head * DH + dloc] = o1;
    }
}

// ---------------------------------------------------------------------------
// Final reduce: Y = 0.25 * (sum of 4 K-split partials + sum_br bias)
// ---------------------------------------------------------------------------
__global__ __launch_bounds__(256)
void reduce_out_kernel(const float* __restrict__ part, const float* __restrict__ wob,
                       float* __restrict__ out)
{
    int idx = blockIdx.x * 256 + threadIdx.x;
    int d = idx & (DMODEL - 1);
    float s = part[idx] + part[idx + 1048576] + part[idx + 2097152] + part[idx + 3145728];
    float b = wob[d] + wob[DMODEL + d] + wob[2 * DMODEL + d] + wob[3 * DMODEL + d];
    out[idx] = 0.25f * (s + b);
}

// ---------------------------------------------------------------------------
extern "C" void kernel_launch(void* const* d_in, const int* in_sizes, int n_in,
                              void* d_out, int out_size)
{
    const float* X        = (const float*)d_in[0];
    const float* W_Q      = (const float*)d_in[1];
    const float* b_Q      = (const float*)d_in[2];
    const float* W_K      = (const float*)d_in[3];
    const float* b_K      = (const float*)d_in[4];
    const float* W_V      = (const float*)d_in[5];
    const float* b_V      = (const float*)d_in[6];
    const float* sinks    = (const float*)d_in[7];
    const float* v_nulls  = (const float*)d_in[8];
    const float* W_O      = (const float*)d_in[9];
    const float* W_O_bias = (const float*)d_in[10];
    float* out = (float*)d_out;

    float *Qp, *Kp, *PARTp;
    cudaGetSymbolAddress((void**)&Qp,    g_Q);
    cudaGetSymbolAddress((void**)&Kp,    g_K);
    cudaGetSymbolAddress((void**)&PARTp, g_part);

    cudaFuncSetAttribute(gemm_qkv, cudaFuncAttributeMaxDynamicSharedMemorySize, GEMM_SMEM_BYTES);
    cudaFuncSetAttribute(gemm_tc_splitk, cudaFuncAttributeMaxDynamicSharedMemorySize, GEMM_SMEM_BYTES);
    cudaFuncSetAttribute(attn_tc_kernel, cudaFuncAttributeMaxDynamicSharedMemorySize, ATTN_SMEM_BYTES);

    // fp16 conversion: X elementwise (z=0), weights transposed (z=1..4)
    convert_ops<<<dim3(4096, 5), 256>>>(X, W_Q, W_K, W_V, W_O);
    // fused Q/K/V projections (fp16 tensor cores; V written transposed fp16)
    gemm_qkv<<<dim3(48, 8, 1), 256, GEMM_SMEM_BYTES>>>(b_Q, b_K, b_V, Qp, Kp);
    // RoPE + key_self folding -> fp16 Q/K
    rope_kernel<<<10240, 256>>>();
    // fp16 tensor-core attention
    attn_tc_kernel<<<dim3(16, 64), 256, ATTN_SMEM_BYTES>>>(sinks, v_nulls);
    // output projection (fp16), split-K=4
    gemm_tc_splitk<<<dim3(8, 8, 4), 256, GEMM_SMEM_BYTES>>>(PARTp, 1024);
    reduce_out_kernel<<<4096, 256>>>(PARTp, W_O_bias, out);
}